// round 11
// baseline (speedup 1.0000x reference)
#include <cuda_runtime.h>
#include <cuda_bf16.h>
#include <cuda_fp16.h>

#define NMAX 50000
#define EMAX 800000
#define GRAPHS 64
#define SCAN_B 1024

// ---------------- device scratch (allocation-free rule) ----------------
static __device__ __half g_h0[NMAX * 64];   // layer-1 output, fp16
static __device__ __half g_h1[NMAX * 128];  // layer-2 output, fp16
static __device__ float g_dinv[NMAX];
static __device__ int   g_cnt[NMAX];
static __device__ int   g_rowptr[NMAX + 1];
static __device__ int   g_cursor[NMAX];
static __device__ int   g_bsum[64];
static __device__ int   g_sync;             // spin barrier (zeroed by k_zero)
static __device__ unsigned long long g_edge[EMAX];  // packed {norm<<32 | src}
static __device__ float g_psum[GRAPHS * 128];
static __device__ float g_pcnt[GRAPHS];

typedef unsigned long long ull;

// ---------------- f32x2 helpers ----------------
__device__ __forceinline__ ull pack2(float x, float y) {
    ull r; asm("mov.b64 %0, {%1,%2};" : "=l"(r) : "f"(x), "f"(y)); return r;
}
__device__ __forceinline__ void unpack2(ull v, float& x, float& y) {
    asm("mov.b64 {%0,%1}, %2;" : "=f"(x), "=f"(y) : "l"(v));
}
__device__ __forceinline__ ull ffma2(ull a, ull b, ull c) {
    ull d; asm("fma.rn.f32x2 %0, %1, %2, %3;" : "=l"(d) : "l"(a), "l"(b), "l"(c));
    return d;
}

// unpack edge record
__device__ __forceinline__ void eunpack(ull r, int& s, float& w) {
    s = (int)(unsigned)r;
    w = __uint_as_float((unsigned)(r >> 32));
}

// ---------------- prep ----------------
__global__ void k_zero(int n) {
    int i = blockIdx.x * blockDim.x + threadIdx.x;
    if (i < n) g_cnt[i] = 0;
    if (i < GRAPHS * 128) g_psum[i] = 0.0f;
    if (i < GRAPHS) g_pcnt[i] = 0.0f;
    if (i == 0) g_sync = 0;
}

// Single-wave CSR builder: count -> scan -> fill, with spin grid barriers.
__global__ void __launch_bounds__(1024) k_prep(const int* __restrict__ src,
                                               const int* __restrict__ dst,
                                               const int* __restrict__ batch,
                                               int n, int E) {
    __shared__ int swarp[32];
    __shared__ int pref[64];
    __shared__ int wtot;
    int t = threadIdx.x;
    int lane = t & 31, wid = t >> 5;
    int nb = gridDim.x;
    int gtid = blockIdx.x * SCAN_B + t;
    int nthr = nb * SCAN_B;

    // ---- phase 1: histograms ----
    for (int e = gtid; e < E; e += nthr) atomicAdd(&g_cnt[dst[e]], 1);
    for (int i = gtid; i < n; i += nthr) atomicAdd(&g_pcnt[batch[i]], 1.0f);

    __threadfence();
    __syncthreads();
    if (t == 0) {
        atomicAdd(&g_sync, 1);
        while (atomicAdd(&g_sync, 0) < nb) { }
    }
    __syncthreads();

    // ---- phase 2: local scan + dinv ----
    int i = gtid;
    int v = (i < n) ? g_cnt[i] : 0;
    if (i < n) g_dinv[i] = rsqrtf((float)v + 1.0f);
    int incl = v;
#pragma unroll
    for (int off = 1; off < 32; off <<= 1) {
        int y = __shfl_up_sync(0xffffffffu, incl, off);
        if (lane >= off) incl += y;
    }
    if (lane == 31) swarp[wid] = incl;
    __syncthreads();
    if (wid == 0) {
        int w = swarp[lane];
#pragma unroll
        for (int off = 1; off < 32; off <<= 1) {
            int y = __shfl_up_sync(0xffffffffu, w, off);
            if (lane >= off) w += y;
        }
        swarp[lane] = w;
    }
    __syncthreads();
    int excl = incl - v + ((wid > 0) ? swarp[wid - 1] : 0);
    if (t == SCAN_B - 1) g_bsum[blockIdx.x] = excl + v;

    __threadfence();
    __syncthreads();
    if (t == 0) {
        atomicAdd(&g_sync, 1);
        while (atomicAdd(&g_sync, 0) < 2 * nb) { }
    }
    __syncthreads();

    // ---- phase 3: prefix block totals, write rowptr/cursor ----
    if (t < 64) {
        int bv = (t < nb) ? g_bsum[t] : 0;
        int binc = bv;
#pragma unroll
        for (int off = 1; off < 32; off <<= 1) {
            int y = __shfl_up_sync(0xffffffffu, binc, off);
            if (lane >= off) binc += y;
        }
        pref[t] = binc - bv;
        if (t == 31) wtot = binc;
    }
    __syncthreads();
    if (t >= 32 && t < 64) pref[t] += wtot;
    __syncthreads();
    if (i < n) {
        int rp = excl + pref[blockIdx.x];
        g_rowptr[i] = rp;
        g_cursor[i] = rp;
    }
    if (gtid == 0) g_rowptr[n] = E;

    __threadfence();
    __syncthreads();
    if (t == 0) {
        atomicAdd(&g_sync, 1);
        while (atomicAdd(&g_sync, 0) < 3 * nb) { }
    }
    __syncthreads();

    // ---- phase 4: fill packed edge records ----
    for (int e = gtid; e < E; e += nthr) {
        int s = src[e], d = dst[e];
        int pos = atomicAdd(&g_cursor[d], 1);
        float nm = g_dinv[s] * g_dinv[d];
        g_edge[pos] = ((ull)__float_as_uint(nm) << 32) | (unsigned)s;
    }
}

// ---------------- Layer 1 fused: agg(C=3) + 3->64 GEMM + relu -> g_h0 -------
__global__ void __launch_bounds__(256) k_layer1(const float* __restrict__ x,
                                                const float* __restrict__ W,
                                                const float* __restrict__ b, int n) {
    const int NPB = 64;
    __shared__ float sa[NPB][3];
    __shared__ float sW[192];
    __shared__ float sb[64];
    int tid = threadIdx.x, wid = tid >> 5, lane = tid & 31;
    int node0 = blockIdx.x * NPB;
    if (tid < 192) sW[tid] = W[tid];
    if (tid < 64) sb[tid] = b[tid];

    for (int k = 0; k < NPB; k += 8) {
        int lr = k + wid;
        int i = node0 + lr;
        if (i < n) {
            int beg = g_rowptr[i], end = g_rowptr[i + 1];
            float a0 = 0.f, a1 = 0.f, a2 = 0.f;
            for (int j = beg + lane; j < end; j += 32) {
                int s; float w; eunpack(g_edge[j], s, w);
                a0 += x[s * 3 + 0] * w;
                a1 += x[s * 3 + 1] * w;
                a2 += x[s * 3 + 2] * w;
            }
#pragma unroll
            for (int off = 16; off > 0; off >>= 1) {
                a0 += __shfl_down_sync(0xffffffffu, a0, off);
                a1 += __shfl_down_sync(0xffffffffu, a1, off);
                a2 += __shfl_down_sync(0xffffffffu, a2, off);
            }
            if (lane == 0) {
                float di = g_dinv[i], sw = di * di;
                sa[lr][0] = a0 + x[i * 3 + 0] * sw;
                sa[lr][1] = a1 + x[i * 3 + 1] * sw;
                sa[lr][2] = a2 + x[i * 3 + 2] * sw;
            }
        }
    }
    __syncthreads();

    int tc = tid & 63, ty = tid >> 6;
    float w0 = sW[tc], w1 = sW[64 + tc], w2 = sW[128 + tc], bb = sb[tc];
#pragma unroll 4
    for (int r = 0; r < 16; r++) {
        int lr = ty * 16 + r;
        int row = node0 + lr;
        if (row >= n) break;
        float v = bb + sa[lr][0] * w0 + sa[lr][1] * w1 + sa[lr][2] * w2;
        g_h0[row * 64 + tc] = __float2half(fmaxf(v, 0.0f));
    }
}

// ---------------- Fused layer: agg(K) + KxC GEMM (+relu) -------------------
// K in {64,128}, C=128. Block: 256 thr, 32 nodes.
// Phase A: warp aggregates 4 nodes (VPL=K/32 fp16/lane) into smem (fp32).
// Phase B: tc=0..31 (4 cols via 2 ull weight vectors / LDG.128),
//          ty=0..7 (4 rows each). Per k-pair per row: LDS.64 + 2 pack + 4 ffma2.
template <int K, int VPL, bool POOL>
__global__ void __launch_bounds__(256) k_layer(const float* __restrict__ W,
                                               const float* __restrict__ b,
                                               const int* __restrict__ batch, int n) {
    const int C = 128, ROWS = 32;
    __shared__ float sh[ROWS][K];
    int tid = threadIdx.x, wid = tid >> 5, lane = tid & 31;
    int row0 = blockIdx.x * ROWS;
    const __half* __restrict__ hp = (K == 64) ? g_h0 : g_h1;

#pragma unroll
    for (int rr = 0; rr < 4; rr++) {
        int lr = wid * 4 + rr;
        int i = row0 + lr;
        if (i < n) {
            int beg = g_rowptr[i], end = g_rowptr[i + 1];
            float di = g_dinv[i], sw = di * di;
            float acc[VPL];
            if (VPL == 4) {
                uint2 u = *(const uint2*)(hp + (size_t)i * K + lane * 4);
                float2 f0 = __half22float2(*reinterpret_cast<__half2*>(&u.x));
                float2 f1 = __half22float2(*reinterpret_cast<__half2*>(&u.y));
                acc[0] = f0.x * sw; acc[1] = f0.y * sw; acc[2] = f1.x * sw; acc[3] = f1.y * sw;
            } else {
                unsigned u = *(const unsigned*)(hp + (size_t)i * K + lane * 2);
                float2 f0 = __half22float2(*reinterpret_cast<__half2*>(&u));
                acc[0] = f0.x * sw; acc[1] = f0.y * sw;
            }
            int j = beg;
            for (; j + 4 <= end; j += 4) {
                int s0, s1, s2, s3; float w0, w1, w2, w3;
                eunpack(g_edge[j], s0, w0);
                eunpack(g_edge[j + 1], s1, w1);
                eunpack(g_edge[j + 2], s2, w2);
                eunpack(g_edge[j + 3], s3, w3);
                if (VPL == 4) {
                    uint2 u0 = *(const uint2*)(hp + (size_t)s0 * K + lane * 4);
                    uint2 u1 = *(const uint2*)(hp + (size_t)s1 * K + lane * 4);
                    uint2 u2 = *(const uint2*)(hp + (size_t)s2 * K + lane * 4);
                    uint2 u3 = *(const uint2*)(hp + (size_t)s3 * K + lane * 4);
                    float2 a0 = __half22float2(*reinterpret_cast<__half2*>(&u0.x));
                    float2 b0 = __half22float2(*reinterpret_cast<__half2*>(&u0.y));
                    float2 a1 = __half22float2(*reinterpret_cast<__half2*>(&u1.x));
                    float2 b1 = __half22float2(*reinterpret_cast<__half2*>(&u1.y));
                    float2 a2 = __half22float2(*reinterpret_cast<__half2*>(&u2.x));
                    float2 b2 = __half22float2(*reinterpret_cast<__half2*>(&u2.y));
                    float2 a3 = __half22float2(*reinterpret_cast<__half2*>(&u3.x));
                    float2 b3 = __half22float2(*reinterpret_cast<__half2*>(&u3.y));
                    acc[0] += a0.x * w0 + a1.x * w1 + a2.x * w2 + a3.x * w3;
                    acc[1] += a0.y * w0 + a1.y * w1 + a2.y * w2 + a3.y * w3;
                    acc[2] += b0.x * w0 + b1.x * w1 + b2.x * w2 + b3.x * w3;
                    acc[3] += b0.y * w0 + b1.y * w1 + b2.y * w2 + b3.y * w3;
                } else {
                    unsigned u0 = *(const unsigned*)(hp + (size_t)s0 * K + lane * 2);
                    unsigned u1 = *(const unsigned*)(hp + (size_t)s1 * K + lane * 2);
                    unsigned u2 = *(const unsigned*)(hp + (size_t)s2 * K + lane * 2);
                    unsigned u3 = *(const unsigned*)(hp + (size_t)s3 * K + lane * 2);
                    float2 a0 = __half22float2(*reinterpret_cast<__half2*>(&u0));
                    float2 a1 = __half22float2(*reinterpret_cast<__half2*>(&u1));
                    float2 a2 = __half22float2(*reinterpret_cast<__half2*>(&u2));
                    float2 a3 = __half22float2(*reinterpret_cast<__half2*>(&u3));
                    acc[0] += a0.x * w0 + a1.x * w1 + a2.x * w2 + a3.x * w3;
                    acc[1] += a0.y * w0 + a1.y * w1 + a2.y * w2 + a3.y * w3;
                }
            }
            for (; j < end; j++) {
                int s; float w; eunpack(g_edge[j], s, w);
                if (VPL == 4) {
                    uint2 u = *(const uint2*)(hp + (size_t)s * K + lane * 4);
                    float2 f0 = __half22float2(*reinterpret_cast<__half2*>(&u.x));
                    float2 f1 = __half22float2(*reinterpret_cast<__half2*>(&u.y));
                    acc[0] += f0.x * w; acc[1] += f0.y * w; acc[2] += f1.x * w; acc[3] += f1.y * w;
                } else {
                    unsigned u = *(const unsigned*)(hp + (size_t)s * K + lane * 2);
                    float2 f0 = __half22float2(*reinterpret_cast<__half2*>(&u));
                    acc[0] += f0.x * w; acc[1] += f0.y * w;
                }
            }
#pragma unroll
            for (int v = 0; v < VPL; v++) sh[lr][lane * VPL + v] = acc[v];
        }
    }
    __syncthreads();

    // Phase B: GEMM from smem. tc covers cols [4tc, 4tc+4); ty*4 rows.
    int tc = tid & 31, ty = tid >> 5;  // 32 col-threads, 8 row-groups
    const ulonglong2* __restrict__ Wv = (const ulonglong2*)W;  // 4 floats/elem
    ull acc0[4], acc1[4];
    {
        float2 ba = *(const float2*)&b[4 * tc];
        float2 bc = *(const float2*)&b[4 * tc + 2];
        ull bi0 = pack2(ba.x, ba.y), bi1 = pack2(bc.x, bc.y);
#pragma unroll
        for (int r = 0; r < 4; r++) { acc0[r] = bi0; acc1[r] = bi1; }
    }
    int rbase = ty * 4;
#pragma unroll 4
    for (int k = 0; k < K; k += 2) {
        ulonglong2 w0 = Wv[k * (C / 4) + tc];
        ulonglong2 w1 = Wv[(k + 1) * (C / 4) + tc];
#pragma unroll
        for (int r = 0; r < 4; r++) {
            float2 s2 = *(const float2*)&sh[rbase + r][k];
            ull ax = pack2(s2.x, s2.x);
            ull ay = pack2(s2.y, s2.y);
            acc0[r] = ffma2(ax, w0.x, acc0[r]);
            acc1[r] = ffma2(ax, w0.y, acc1[r]);
            acc0[r] = ffma2(ay, w1.x, acc0[r]);
            acc1[r] = ffma2(ay, w1.y, acc1[r]);
        }
    }

    if (!POOL) {
#pragma unroll
        for (int r = 0; r < 4; r++) {
            int row = row0 + rbase + r;
            if (row < n) {
                float x0, y0, x1, y1;
                unpack2(acc0[r], x0, y0);
                unpack2(acc1[r], x1, y1);
                __half2 o0 = __floats2half2_rn(fmaxf(x0, 0.0f), fmaxf(y0, 0.0f));
                __half2 o1 = __floats2half2_rn(fmaxf(x1, 0.0f), fmaxf(y1, 0.0f));
                uint2 st;
                st.x = *(unsigned*)&o0;
                st.y = *(unsigned*)&o1;
                *(uint2*)&g_h1[(size_t)row * C + 4 * tc] = st;
            }
        }
    } else {
        int curg = -1;
        float r0 = 0.f, r1 = 0.f, r2 = 0.f, r3 = 0.f;
#pragma unroll
        for (int r = 0; r < 4; r++) {
            int row = row0 + rbase + r;
            if (row >= n) break;
            float x0, y0, x1, y1;
            unpack2(acc0[r], x0, y0);
            unpack2(acc1[r], x1, y1);
            x0 = fmaxf(x0, 0.0f); y0 = fmaxf(y0, 0.0f);
            x1 = fmaxf(x1, 0.0f); y1 = fmaxf(y1, 0.0f);
            int g = __ldg(&batch[row]);
            if (g != curg) {
                if (curg >= 0) {
                    atomicAdd(&g_psum[curg * 128 + 4 * tc + 0], r0);
                    atomicAdd(&g_psum[curg * 128 + 4 * tc + 1], r1);
                    atomicAdd(&g_psum[curg * 128 + 4 * tc + 2], r2);
                    atomicAdd(&g_psum[curg * 128 + 4 * tc + 3], r3);
                }
                curg = g; r0 = r1 = r2 = r3 = 0.0f;
            }
            r0 += x0; r1 += y0; r2 += x1; r3 += y1;
        }
        if (curg >= 0) {
            atomicAdd(&g_psum[curg * 128 + 4 * tc + 0], r0);
            atomicAdd(&g_psum[curg * 128 + 4 * tc + 1], r1);
            atomicAdd(&g_psum[curg * 128 + 4 * tc + 2], r2);
            atomicAdd(&g_psum[curg * 128 + 4 * tc + 3], r3);
        }
    }
}

// ---------------- MLP head ----------------
__global__ void k_fc(const float* __restrict__ Wf1, const float* __restrict__ bf1,
                     const float* __restrict__ Wf2, const float* __restrict__ bf2,
                     float* __restrict__ out) {
    int g = blockIdx.x;
    int t = threadIdx.x;  // 128
    __shared__ float p[128];
    __shared__ float f1[64];
    float inv = 1.0f / fmaxf(g_pcnt[g], 1.0f);
    p[t] = g_psum[g * 128 + t] * inv;
    __syncthreads();
    if (t < 64) {
        float acc = bf1[t];
#pragma unroll
        for (int k = 0; k < 128; k++) acc += p[k] * Wf1[k * 64 + t];
        f1[t] = fmaxf(acc, 0.0f);
    }
    __syncthreads();
    if (t < 10) {
        float acc = bf2[t];
#pragma unroll
        for (int k = 0; k < 64; k++) acc += f1[k] * Wf2[k * 10 + t];
        out[g * 10 + t] = acc;
    }
}

extern "C" void kernel_launch(void* const* d_in, const int* in_sizes, int n_in,
                              void* d_out, int out_size) {
    const float* x   = (const float*)d_in[0];
    const int* ei    = (const int*)d_in[1];
    const int* batch = (const int*)d_in[2];
    const float* W1  = (const float*)d_in[3];
    const float* b1  = (const float*)d_in[4];
    const float* W2  = (const float*)d_in[5];
    const float* b2  = (const float*)d_in[6];
    const float* W3  = (const float*)d_in[7];
    const float* b3  = (const float*)d_in[8];
    const float* Wf1 = (const float*)d_in[9];
    const float* bf1 = (const float*)d_in[10];
    const float* Wf2 = (const float*)d_in[11];
    const float* bf2 = (const float*)d_in[12];
    float* out = (float*)d_out;

    int N = in_sizes[0] / 3;
    int E = in_sizes[1] / 2;
    const int* src = ei;
    const int* dst = ei + E;
    int NB = (N + SCAN_B - 1) / SCAN_B;  // <= 49

    // zero + single-wave CSR builder
    k_zero<<<(N + 255) / 256, 256>>>(N);
    k_prep<<<NB, SCAN_B>>>(src, dst, batch, N, E);

    // Fused layers
    k_layer1<<<(N + 63) / 64, 256>>>(x, W1, b1, N);
    k_layer<64, 2, false><<<(N + 31) / 32, 256>>>(W2, b2, batch, N);
    k_layer<128, 4, true><<<(N + 31) / 32, 256>>>(W3, b3, batch, N);

    // Head
    k_fc<<<GRAPHS, 128>>>(Wf1, bf1, Wf2, bf2, out);
}

// round 12
// speedup vs baseline: 1.0548x; 1.0548x over previous
#include <cuda_runtime.h>
#include <cuda_bf16.h>
#include <cuda_fp16.h>
#include <mma.h>

using namespace nvcuda;

#define NMAX 50000
#define EMAX 800000
#define GRAPHS 64
#define SCAN_B 1024

// ---------------- device scratch (allocation-free rule) ----------------
static __device__ __half g_h0[NMAX * 64];   // layer-1 output, fp16
static __device__ __half g_h1[NMAX * 128];  // layer-2 output, fp16
static __device__ __half g_w2h[64 * 128];   // W2 in fp16
static __device__ __half g_w3h[128 * 128];  // W3 in fp16
static __device__ float g_dinv[NMAX];
static __device__ int   g_cnt[NMAX];
static __device__ int   g_rowptr[NMAX + 1];
static __device__ int   g_cursor[NMAX];
static __device__ int   g_bsum[64];
static __device__ int   g_sync;             // spin barrier (zeroed by k_zero)
static __device__ unsigned long long g_edge[EMAX];  // packed {norm<<32 | src}
static __device__ float g_psum[GRAPHS * 128];
static __device__ float g_pcnt[GRAPHS];

typedef unsigned long long ull;

// unpack edge record
__device__ __forceinline__ void eunpack(ull r, int& s, float& w) {
    s = (int)(unsigned)r;
    w = __uint_as_float((unsigned)(r >> 32));
}

// ---------------- prep ----------------
__global__ void k_zero(const float* __restrict__ W2, const float* __restrict__ W3, int n) {
    int i = blockIdx.x * blockDim.x + threadIdx.x;
    if (i < n) g_cnt[i] = 0;
    if (i < GRAPHS * 128) g_psum[i] = 0.0f;
    if (i < GRAPHS) g_pcnt[i] = 0.0f;
    if (i == 0) g_sync = 0;
    if (i < 64 * 128) g_w2h[i] = __float2half(W2[i]);
    if (i < 128 * 128) g_w3h[i] = __float2half(W3[i]);
}

// Single-wave CSR builder: count -> scan -> fill, with spin grid barriers.
__global__ void __launch_bounds__(1024) k_prep(const int* __restrict__ src,
                                               const int* __restrict__ dst,
                                               const int* __restrict__ batch,
                                               int n, int E) {
    __shared__ int swarp[32];
    __shared__ int pref[64];
    __shared__ int wtot;
    int t = threadIdx.x;
    int lane = t & 31, wid = t >> 5;
    int nb = gridDim.x;
    int gtid = blockIdx.x * SCAN_B + t;
    int nthr = nb * SCAN_B;

    // ---- phase 1: histograms ----
    for (int e = gtid; e < E; e += nthr) atomicAdd(&g_cnt[dst[e]], 1);
    for (int i = gtid; i < n; i += nthr) atomicAdd(&g_pcnt[batch[i]], 1.0f);

    __threadfence();
    __syncthreads();
    if (t == 0) {
        atomicAdd(&g_sync, 1);
        while (atomicAdd(&g_sync, 0) < nb) { }
    }
    __syncthreads();

    // ---- phase 2: local scan + dinv ----
    int i = gtid;
    int v = (i < n) ? g_cnt[i] : 0;
    if (i < n) g_dinv[i] = rsqrtf((float)v + 1.0f);
    int incl = v;
#pragma unroll
    for (int off = 1; off < 32; off <<= 1) {
        int y = __shfl_up_sync(0xffffffffu, incl, off);
        if (lane >= off) incl += y;
    }
    if (lane == 31) swarp[wid] = incl;
    __syncthreads();
    if (wid == 0) {
        int w = swarp[lane];
#pragma unroll
        for (int off = 1; off < 32; off <<= 1) {
            int y = __shfl_up_sync(0xffffffffu, w, off);
            if (lane >= off) w += y;
        }
        swarp[lane] = w;
    }
    __syncthreads();
    int excl = incl - v + ((wid > 0) ? swarp[wid - 1] : 0);
    if (t == SCAN_B - 1) g_bsum[blockIdx.x] = excl + v;

    __threadfence();
    __syncthreads();
    if (t == 0) {
        atomicAdd(&g_sync, 1);
        while (atomicAdd(&g_sync, 0) < 2 * nb) { }
    }
    __syncthreads();

    // ---- phase 3: prefix block totals, write rowptr/cursor ----
    if (t < 64) {
        int bv = (t < nb) ? g_bsum[t] : 0;
        int binc = bv;
#pragma unroll
        for (int off = 1; off < 32; off <<= 1) {
            int y = __shfl_up_sync(0xffffffffu, binc, off);
            if (lane >= off) binc += y;
        }
        pref[t] = binc - bv;
        if (t == 31) wtot = binc;
    }
    __syncthreads();
    if (t >= 32 && t < 64) pref[t] += wtot;
    __syncthreads();
    if (i < n) {
        int rp = excl + pref[blockIdx.x];
        g_rowptr[i] = rp;
        g_cursor[i] = rp;
    }
    if (gtid == 0) g_rowptr[n] = E;

    __threadfence();
    __syncthreads();
    if (t == 0) {
        atomicAdd(&g_sync, 1);
        while (atomicAdd(&g_sync, 0) < 3 * nb) { }
    }
    __syncthreads();

    // ---- phase 4: fill packed edge records ----
    for (int e = gtid; e < E; e += nthr) {
        int s = src[e], d = dst[e];
        int pos = atomicAdd(&g_cursor[d], 1);
        float nm = g_dinv[s] * g_dinv[d];
        g_edge[pos] = ((ull)__float_as_uint(nm) << 32) | (unsigned)s;
    }
}

// ---------------- Layer 1 fused: agg(C=3) + 3->64 GEMM + relu -> g_h0 -------
__global__ void __launch_bounds__(256) k_layer1(const float* __restrict__ x,
                                                const float* __restrict__ W,
                                                const float* __restrict__ b, int n) {
    const int NPB = 64;
    __shared__ float sa[NPB][3];
    __shared__ float sW[192];
    __shared__ float sb[64];
    int tid = threadIdx.x, wid = tid >> 5, lane = tid & 31;
    int node0 = blockIdx.x * NPB;
    if (tid < 192) sW[tid] = W[tid];
    if (tid < 64) sb[tid] = b[tid];

    for (int k = 0; k < NPB; k += 8) {
        int lr = k + wid;
        int i = node0 + lr;
        if (i < n) {
            int beg = g_rowptr[i], end = g_rowptr[i + 1];
            float a0 = 0.f, a1 = 0.f, a2 = 0.f;
            for (int j = beg + lane; j < end; j += 32) {
                int s; float w; eunpack(g_edge[j], s, w);
                a0 += x[s * 3 + 0] * w;
                a1 += x[s * 3 + 1] * w;
                a2 += x[s * 3 + 2] * w;
            }
#pragma unroll
            for (int off = 16; off > 0; off >>= 1) {
                a0 += __shfl_down_sync(0xffffffffu, a0, off);
                a1 += __shfl_down_sync(0xffffffffu, a1, off);
                a2 += __shfl_down_sync(0xffffffffu, a2, off);
            }
            if (lane == 0) {
                float di = g_dinv[i], sw = di * di;
                sa[lr][0] = a0 + x[i * 3 + 0] * sw;
                sa[lr][1] = a1 + x[i * 3 + 1] * sw;
                sa[lr][2] = a2 + x[i * 3 + 2] * sw;
            }
        }
    }
    __syncthreads();

    int tc = tid & 63, ty = tid >> 6;
    float w0 = sW[tc], w1 = sW[64 + tc], w2 = sW[128 + tc], bb = sb[tc];
#pragma unroll 4
    for (int r = 0; r < 16; r++) {
        int lr = ty * 16 + r;
        int row = node0 + lr;
        if (row >= n) break;
        float v = bb + sa[lr][0] * w0 + sa[lr][1] * w1 + sa[lr][2] * w2;
        g_h0[row * 64 + tc] = __float2half(fmaxf(v, 0.0f));
    }
}

// ---------------- Fused layer: agg(K) + KxC GEMM via WMMA (+relu) ----------
// K in {64,128}, C=128. Block: 256 thr, 16 nodes.
// Phase A (R9 shape): warp aggregates 2 nodes, fp32 accum, stores fp16 to shA.
// Phase B: 8 warps x one 16x16 wmma tile over C=128; fp16 A/W, fp32 accum.
// Epilogue: bias + relu (+ pooled atomics) from smem fp32.
template <int K, int VPL, bool POOL>
__global__ void __launch_bounds__(256) k_layer(const float* __restrict__ b,
                                               const int* __restrict__ batch, int n) {
    const int C = 128, ROWS = 16;
    __shared__ __half shA[ROWS * K];
    __shared__ float sC[ROWS * C];
    int tid = threadIdx.x, wid = tid >> 5, lane = tid & 31;
    int row0 = blockIdx.x * ROWS;
    const __half* __restrict__ hp = (K == 64) ? g_h0 : g_h1;
    const __half* __restrict__ Wh = (K == 64) ? g_w2h : g_w3h;

#pragma unroll
    for (int rr = 0; rr < 2; rr++) {
        int lr = wid * 2 + rr;
        int i = row0 + lr;
        if (i < n) {
            int beg = g_rowptr[i], end = g_rowptr[i + 1];
            float di = g_dinv[i], sw = di * di;
            float acc[VPL];
            if (VPL == 4) {
                uint2 u = *(const uint2*)(hp + (size_t)i * K + lane * 4);
                float2 f0 = __half22float2(*reinterpret_cast<__half2*>(&u.x));
                float2 f1 = __half22float2(*reinterpret_cast<__half2*>(&u.y));
                acc[0] = f0.x * sw; acc[1] = f0.y * sw; acc[2] = f1.x * sw; acc[3] = f1.y * sw;
            } else {
                unsigned u = *(const unsigned*)(hp + (size_t)i * K + lane * 2);
                float2 f0 = __half22float2(*reinterpret_cast<__half2*>(&u));
                acc[0] = f0.x * sw; acc[1] = f0.y * sw;
            }
            int j = beg;
            for (; j + 4 <= end; j += 4) {
                int s0, s1, s2, s3; float w0, w1, w2, w3;
                eunpack(g_edge[j], s0, w0);
                eunpack(g_edge[j + 1], s1, w1);
                eunpack(g_edge[j + 2], s2, w2);
                eunpack(g_edge[j + 3], s3, w3);
                if (VPL == 4) {
                    uint2 u0 = *(const uint2*)(hp + (size_t)s0 * K + lane * 4);
                    uint2 u1 = *(const uint2*)(hp + (size_t)s1 * K + lane * 4);
                    uint2 u2 = *(const uint2*)(hp + (size_t)s2 * K + lane * 4);
                    uint2 u3 = *(const uint2*)(hp + (size_t)s3 * K + lane * 4);
                    float2 a0 = __half22float2(*reinterpret_cast<__half2*>(&u0.x));
                    float2 b0 = __half22float2(*reinterpret_cast<__half2*>(&u0.y));
                    float2 a1 = __half22float2(*reinterpret_cast<__half2*>(&u1.x));
                    float2 b1 = __half22float2(*reinterpret_cast<__half2*>(&u1.y));
                    float2 a2 = __half22float2(*reinterpret_cast<__half2*>(&u2.x));
                    float2 b2 = __half22float2(*reinterpret_cast<__half2*>(&u2.y));
                    float2 a3 = __half22float2(*reinterpret_cast<__half2*>(&u3.x));
                    float2 b3 = __half22float2(*reinterpret_cast<__half2*>(&u3.y));
                    acc[0] += a0.x * w0 + a1.x * w1 + a2.x * w2 + a3.x * w3;
                    acc[1] += a0.y * w0 + a1.y * w1 + a2.y * w2 + a3.y * w3;
                    acc[2] += b0.x * w0 + b1.x * w1 + b2.x * w2 + b3.x * w3;
                    acc[3] += b0.y * w0 + b1.y * w1 + b2.y * w2 + b3.y * w3;
                } else {
                    unsigned u0 = *(const unsigned*)(hp + (size_t)s0 * K + lane * 2);
                    unsigned u1 = *(const unsigned*)(hp + (size_t)s1 * K + lane * 2);
                    unsigned u2 = *(const unsigned*)(hp + (size_t)s2 * K + lane * 2);
                    unsigned u3 = *(const unsigned*)(hp + (size_t)s3 * K + lane * 2);
                    float2 a0 = __half22float2(*reinterpret_cast<__half2*>(&u0));
                    float2 a1 = __half22float2(*reinterpret_cast<__half2*>(&u1));
                    float2 a2 = __half22float2(*reinterpret_cast<__half2*>(&u2));
                    float2 a3 = __half22float2(*reinterpret_cast<__half2*>(&u3));
                    acc[0] += a0.x * w0 + a1.x * w1 + a2.x * w2 + a3.x * w3;
                    acc[1] += a0.y * w0 + a1.y * w1 + a2.y * w2 + a3.y * w3;
                }
            }
            for (; j < end; j++) {
                int s; float w; eunpack(g_edge[j], s, w);
                if (VPL == 4) {
                    uint2 u = *(const uint2*)(hp + (size_t)s * K + lane * 4);
                    float2 f0 = __half22float2(*reinterpret_cast<__half2*>(&u.x));
                    float2 f1 = __half22float2(*reinterpret_cast<__half2*>(&u.y));
                    acc[0] += f0.x * w; acc[1] += f0.y * w; acc[2] += f1.x * w; acc[3] += f1.y * w;
                } else {
                    unsigned u = *(const unsigned*)(hp + (size_t)s * K + lane * 2);
                    float2 f0 = __half22float2(*reinterpret_cast<__half2*>(&u));
                    acc[0] += f0.x * w; acc[1] += f0.y * w;
                }
            }
            // store fp16 to shA
#pragma unroll
            for (int v = 0; v < VPL; v += 2) {
                __half2 hh = __floats2half2_rn(acc[v], acc[v + 1]);
                *(__half2*)&shA[lr * K + lane * VPL + v] = hh;
            }
        } else {
            // zero pad rows beyond n (outputs discarded, keep mma clean)
#pragma unroll
            for (int v = 0; v < VPL; v += 2)
                *(__half2*)&shA[lr * K + lane * VPL + v] = __floats2half2_rn(0.f, 0.f);
        }
    }
    __syncthreads();

    // Phase B: WMMA. warp wid computes rows 0..15 x cols [16*wid, 16*wid+16)
    {
        wmma::fragment<wmma::matrix_a, 16, 16, 16, __half, wmma::row_major> fa;
        wmma::fragment<wmma::matrix_b, 16, 16, 16, __half, wmma::row_major> fb;
        wmma::fragment<wmma::accumulator, 16, 16, 16, float> fc;
        wmma::fill_fragment(fc, 0.0f);
#pragma unroll
        for (int k = 0; k < K; k += 16) {
            wmma::load_matrix_sync(fa, shA + k, K);
            wmma::load_matrix_sync(fb, Wh + k * C + wid * 16, C);
            wmma::mma_sync(fc, fa, fb, fc);
        }
        wmma::store_matrix_sync(sC + wid * 16, fc, C, wmma::mem_row_major);
    }
    __syncthreads();

    // Epilogue: bias + relu (+ pool) from sC
    int tc = tid & 63, ty = tid >> 6;  // cols 2tc,2tc+1; rows ty*4..ty*4+3
    float2 bb = *(const float2*)&b[2 * tc];
    if (!POOL) {
#pragma unroll
        for (int r = 0; r < 4; r++) {
            int lr = ty * 4 + r;
            int row = row0 + lr;
            if (row < n) {
                float xv = sC[lr * C + 2 * tc] + bb.x;
                float yv = sC[lr * C + 2 * tc + 1] + bb.y;
                __half2 o = __floats2half2_rn(fmaxf(xv, 0.0f), fmaxf(yv, 0.0f));
                *(__half2*)&g_h1[(size_t)row * C + 2 * tc] = o;
            }
        }
    } else {
        int curg = -1;
        float rx = 0.0f, ry = 0.0f;
#pragma unroll
        for (int r = 0; r < 4; r++) {
            int lr = ty * 4 + r;
            int row = row0 + lr;
            if (row >= n) break;
            float xv = fmaxf(sC[lr * C + 2 * tc] + bb.x, 0.0f);
            float yv = fmaxf(sC[lr * C + 2 * tc + 1] + bb.y, 0.0f);
            int g = __ldg(&batch[row]);
            if (g != curg) {
                if (curg >= 0) {
                    atomicAdd(&g_psum[curg * 128 + 2 * tc], rx);
                    atomicAdd(&g_psum[curg * 128 + 2 * tc + 1], ry);
                }
                curg = g; rx = 0.0f; ry = 0.0f;
            }
            rx += xv; ry += yv;
        }
        if (curg >= 0) {
            atomicAdd(&g_psum[curg * 128 + 2 * tc], rx);
            atomicAdd(&g_psum[curg * 128 + 2 * tc + 1], ry);
        }
    }
}

// ---------------- MLP head ----------------
__global__ void k_fc(const float* __restrict__ Wf1, const float* __restrict__ bf1,
                     const float* __restrict__ Wf2, const float* __restrict__ bf2,
                     float* __restrict__ out) {
    int g = blockIdx.x;
    int t = threadIdx.x;  // 128
    __shared__ float p[128];
    __shared__ float f1[64];
    float inv = 1.0f / fmaxf(g_pcnt[g], 1.0f);
    p[t] = g_psum[g * 128 + t] * inv;
    __syncthreads();
    if (t < 64) {
        float acc = bf1[t];
#pragma unroll
        for (int k = 0; k < 128; k++) acc += p[k] * Wf1[k * 64 + t];
        f1[t] = fmaxf(acc, 0.0f);
    }
    __syncthreads();
    if (t < 10) {
        float acc = bf2[t];
#pragma unroll
        for (int k = 0; k < 64; k++) acc += f1[k] * Wf2[k * 10 + t];
        out[g * 10 + t] = acc;
    }
}

extern "C" void kernel_launch(void* const* d_in, const int* in_sizes, int n_in,
                              void* d_out, int out_size) {
    const float* x   = (const float*)d_in[0];
    const int* ei    = (const int*)d_in[1];
    const int* batch = (const int*)d_in[2];
    const float* W1  = (const float*)d_in[3];
    const float* b1  = (const float*)d_in[4];
    const float* W2  = (const float*)d_in[5];
    const float* b2  = (const float*)d_in[6];
    const float* W3  = (const float*)d_in[7];
    const float* b3  = (const float*)d_in[8];
    const float* Wf1 = (const float*)d_in[9];
    const float* bf1 = (const float*)d_in[10];
    const float* Wf2 = (const float*)d_in[11];
    const float* bf2 = (const float*)d_in[12];
    float* out = (float*)d_out;

    int N = in_sizes[0] / 3;
    int E = in_sizes[1] / 2;
    const int* src = ei;
    const int* dst = ei + E;
    int NB = (N + SCAN_B - 1) / SCAN_B;  // <= 49

    // zero + weight fp16 conversion + single-wave CSR builder
    k_zero<<<(N + 255) / 256, 256>>>(W2, W3, N);
    k_prep<<<NB, SCAN_B>>>(src, dst, batch, N, E);

    // Fused layers
    k_layer1<<<(N + 63) / 64, 256>>>(x, W1, b1, N);
    k_layer<64, 2, false><<<(N + 15) / 16, 256>>>(b2, batch, N);
    k_layer<128, 4, true><<<(N + 15) / 16, 256>>>(b3, batch, N);

    // Head
    k_fc<<<GRAPHS, 128>>>(Wf1, bf1, Wf2, bf2, out);
}

// round 13
// speedup vs baseline: 1.3539x; 1.2835x over previous
#include <cuda_runtime.h>
#include <cuda_bf16.h>
#include <cuda_fp16.h>
#include <mma.h>

using namespace nvcuda;

#define NMAX 50000
#define EMAX 800000
#define GRAPHS 64
#define SCAN_B 1024

// ---------------- device scratch (allocation-free rule) ----------------
static __device__ __half g_h0[NMAX * 64];   // layer-1 output, fp16
static __device__ __half g_h1[NMAX * 128];  // layer-2 output, fp16
static __device__ __half g_w2h[64 * 128];   // W2 in fp16
static __device__ __half g_w3h[128 * 128];  // W3 in fp16
static __device__ float g_dinv[NMAX];
static __device__ int   g_cnt[NMAX];
static __device__ int   g_rowptr[NMAX + 1];
static __device__ int   g_cursor[NMAX];
static __device__ int   g_bsum[64];
static __device__ int   g_sync;             // spin barrier (zeroed by k_zero)
static __device__ unsigned long long g_edge[EMAX];  // packed {norm<<32 | src}
static __device__ float g_psum[GRAPHS * 128];
static __device__ float g_pcnt[GRAPHS];

typedef unsigned long long ull;

// unpack edge record
__device__ __forceinline__ void eunpack(ull r, int& s, float& w) {
    s = (int)(unsigned)r;
    w = __uint_as_float((unsigned)(r >> 32));
}

// ---------------- prep ----------------
__global__ void k_zero(const float* __restrict__ W2, const float* __restrict__ W3, int n) {
    int i = blockIdx.x * blockDim.x + threadIdx.x;
    if (i < n) g_cnt[i] = 0;
    if (i < GRAPHS * 128) g_psum[i] = 0.0f;
    if (i < GRAPHS) g_pcnt[i] = 0.0f;
    if (i == 0) g_sync = 0;
    if (i < 64 * 128) g_w2h[i] = __float2half(W2[i]);
    if (i < 128 * 128) g_w3h[i] = __float2half(W3[i]);
}

// Single-wave CSR builder: count -> scan -> fill, with spin grid barriers.
__global__ void __launch_bounds__(1024) k_prep(const int* __restrict__ src,
                                               const int* __restrict__ dst,
                                               const int* __restrict__ batch,
                                               int n, int E) {
    __shared__ int swarp[32];
    __shared__ int pref[64];
    __shared__ int wtot;
    int t = threadIdx.x;
    int lane = t & 31, wid = t >> 5;
    int nb = gridDim.x;
    int gtid = blockIdx.x * SCAN_B + t;
    int nthr = nb * SCAN_B;

    // ---- phase 1: histograms ----
    for (int e = gtid; e < E; e += nthr) atomicAdd(&g_cnt[dst[e]], 1);
    for (int i = gtid; i < n; i += nthr) atomicAdd(&g_pcnt[batch[i]], 1.0f);

    __threadfence();
    __syncthreads();
    if (t == 0) {
        atomicAdd(&g_sync, 1);
        while (atomicAdd(&g_sync, 0) < nb) { }
    }
    __syncthreads();

    // ---- phase 2: local scan + dinv ----
    int i = gtid;
    int v = (i < n) ? g_cnt[i] : 0;
    if (i < n) g_dinv[i] = rsqrtf((float)v + 1.0f);
    int incl = v;
#pragma unroll
    for (int off = 1; off < 32; off <<= 1) {
        int y = __shfl_up_sync(0xffffffffu, incl, off);
        if (lane >= off) incl += y;
    }
    if (lane == 31) swarp[wid] = incl;
    __syncthreads();
    if (wid == 0) {
        int w = swarp[lane];
#pragma unroll
        for (int off = 1; off < 32; off <<= 1) {
            int y = __shfl_up_sync(0xffffffffu, w, off);
            if (lane >= off) w += y;
        }
        swarp[lane] = w;
    }
    __syncthreads();
    int excl = incl - v + ((wid > 0) ? swarp[wid - 1] : 0);
    if (t == SCAN_B - 1) g_bsum[blockIdx.x] = excl + v;

    __threadfence();
    __syncthreads();
    if (t == 0) {
        atomicAdd(&g_sync, 1);
        while (atomicAdd(&g_sync, 0) < 2 * nb) { }
    }
    __syncthreads();

    // ---- phase 3: prefix block totals, write rowptr/cursor ----
    if (t < 64) {
        int bv = (t < nb) ? g_bsum[t] : 0;
        int binc = bv;
#pragma unroll
        for (int off = 1; off < 32; off <<= 1) {
            int y = __shfl_up_sync(0xffffffffu, binc, off);
            if (lane >= off) binc += y;
        }
        pref[t] = binc - bv;
        if (t == 31) wtot = binc;
    }
    __syncthreads();
    if (t >= 32 && t < 64) pref[t] += wtot;
    __syncthreads();
    if (i < n) {
        int rp = excl + pref[blockIdx.x];
        g_rowptr[i] = rp;
        g_cursor[i] = rp;
    }
    if (gtid == 0) g_rowptr[n] = E;

    __threadfence();
    __syncthreads();
    if (t == 0) {
        atomicAdd(&g_sync, 1);
        while (atomicAdd(&g_sync, 0) < 3 * nb) { }
    }
    __syncthreads();

    // ---- phase 4: fill packed edge records ----
    for (int e = gtid; e < E; e += nthr) {
        int s = src[e], d = dst[e];
        int pos = atomicAdd(&g_cursor[d], 1);
        float nm = g_dinv[s] * g_dinv[d];
        g_edge[pos] = ((ull)__float_as_uint(nm) << 32) | (unsigned)s;
    }
}

// ---------------- Layer 1 fused: agg(C=3) + 3->64 GEMM + relu -> g_h0 -------
__global__ void __launch_bounds__(256) k_layer1(const float* __restrict__ x,
                                                const float* __restrict__ W,
                                                const float* __restrict__ b, int n) {
    const int NPB = 64;
    __shared__ float sa[NPB][3];
    __shared__ float sW[192];
    __shared__ float sb[64];
    int tid = threadIdx.x, wid = tid >> 5, lane = tid & 31;
    int node0 = blockIdx.x * NPB;
    if (tid < 192) sW[tid] = W[tid];
    if (tid < 64) sb[tid] = b[tid];

    for (int k = 0; k < NPB; k += 8) {
        int lr = k + wid;
        int i = node0 + lr;
        if (i < n) {
            int beg = g_rowptr[i], end = g_rowptr[i + 1];
            float a0 = 0.f, a1 = 0.f, a2 = 0.f;
            for (int j = beg + lane; j < end; j += 32) {
                int s; float w; eunpack(g_edge[j], s, w);
                a0 += x[s * 3 + 0] * w;
                a1 += x[s * 3 + 1] * w;
                a2 += x[s * 3 + 2] * w;
            }
#pragma unroll
            for (int off = 16; off > 0; off >>= 1) {
                a0 += __shfl_down_sync(0xffffffffu, a0, off);
                a1 += __shfl_down_sync(0xffffffffu, a1, off);
                a2 += __shfl_down_sync(0xffffffffu, a2, off);
            }
            if (lane == 0) {
                float di = g_dinv[i], sw = di * di;
                sa[lr][0] = a0 + x[i * 3 + 0] * sw;
                sa[lr][1] = a1 + x[i * 3 + 1] * sw;
                sa[lr][2] = a2 + x[i * 3 + 2] * sw;
            }
        }
    }
    __syncthreads();

    int tc = tid & 63, ty = tid >> 6;
    float w0 = sW[tc], w1 = sW[64 + tc], w2 = sW[128 + tc], bb = sb[tc];
#pragma unroll 4
    for (int r = 0; r < 16; r++) {
        int lr = ty * 16 + r;
        int row = node0 + lr;
        if (row >= n) break;
        float v = bb + sa[lr][0] * w0 + sa[lr][1] * w1 + sa[lr][2] * w2;
        g_h0[row * 64 + tc] = __float2half(fmaxf(v, 0.0f));
    }
}

// ---------------- Fused layer: agg(K) + KxC GEMM via WMMA (+relu) ----------
// K in {64,128}, C=128. Block: 256 thr, 16 nodes.
// Phase A (R9 shape): warp aggregates 2 nodes, fp32 accum, stores fp16 to shA
//   (padded K+8 row stride, LDSM-friendly).
// W staged once per block into padded smem [K][136] (coalesced uint4 copy).
// Phase B: 8 warps x one 16x16 wmma tile over C=128; fa/fb from smem (LDSM).
// sC (fp32, padded [16][132]) ALIASES the sW region (dead after mma).
template <int K, int VPL, bool POOL>
__global__ void __launch_bounds__(256) k_layer(const float* __restrict__ b,
                                               const int* __restrict__ batch, int n) {
    const int C = 128, ROWS = 16;
    const int Kp = K + 8;      // half elems; row stride (K+8)*2 bytes, mult of 16
    const int Cp = 136;        // half elems; 272B row stride
    const int Cp4 = 132;       // float elems; 528B row stride
    __shared__ __align__(16) __half shA[ROWS * Kp];
    __shared__ __align__(16) __half sW[K * Cp];   // reused as sC after mma
    float* sC = (float*)sW;    // 16*132*4 = 8448B <= K*Cp*2

    int tid = threadIdx.x, wid = tid >> 5, lane = tid & 31;
    int row0 = blockIdx.x * ROWS;
    const __half* __restrict__ hp = (K == 64) ? g_h0 : g_h1;
    const __half* __restrict__ Wh = (K == 64) ? g_w2h : g_w3h;

    // ---- stage W into padded smem (K rows x 16 uint4 each) ----
    {
        const uint4* Wg = (const uint4*)Wh;  // 8 halves per uint4, 16 per row
        for (int idx = tid; idx < K * 16; idx += 256) {
            int r = idx >> 4, c = idx & 15;
            ((uint4*)(sW + r * Cp))[c] = Wg[r * 16 + c];
        }
    }

    // ---- phase A: aggregation ----
#pragma unroll
    for (int rr = 0; rr < 2; rr++) {
        int lr = wid * 2 + rr;
        int i = row0 + lr;
        if (i < n) {
            int beg = g_rowptr[i], end = g_rowptr[i + 1];
            float di = g_dinv[i], sw = di * di;
            float acc[VPL];
            if (VPL == 4) {
                uint2 u = *(const uint2*)(hp + (size_t)i * K + lane * 4);
                float2 f0 = __half22float2(*reinterpret_cast<__half2*>(&u.x));
                float2 f1 = __half22float2(*reinterpret_cast<__half2*>(&u.y));
                acc[0] = f0.x * sw; acc[1] = f0.y * sw; acc[2] = f1.x * sw; acc[3] = f1.y * sw;
            } else {
                unsigned u = *(const unsigned*)(hp + (size_t)i * K + lane * 2);
                float2 f0 = __half22float2(*reinterpret_cast<__half2*>(&u));
                acc[0] = f0.x * sw; acc[1] = f0.y * sw;
            }
            int j = beg;
            for (; j + 4 <= end; j += 4) {
                int s0, s1, s2, s3; float w0, w1, w2, w3;
                eunpack(g_edge[j], s0, w0);
                eunpack(g_edge[j + 1], s1, w1);
                eunpack(g_edge[j + 2], s2, w2);
                eunpack(g_edge[j + 3], s3, w3);
                if (VPL == 4) {
                    uint2 u0 = *(const uint2*)(hp + (size_t)s0 * K + lane * 4);
                    uint2 u1 = *(const uint2*)(hp + (size_t)s1 * K + lane * 4);
                    uint2 u2 = *(const uint2*)(hp + (size_t)s2 * K + lane * 4);
                    uint2 u3 = *(const uint2*)(hp + (size_t)s3 * K + lane * 4);
                    float2 a0 = __half22float2(*reinterpret_cast<__half2*>(&u0.x));
                    float2 b0 = __half22float2(*reinterpret_cast<__half2*>(&u0.y));
                    float2 a1 = __half22float2(*reinterpret_cast<__half2*>(&u1.x));
                    float2 b1 = __half22float2(*reinterpret_cast<__half2*>(&u1.y));
                    float2 a2 = __half22float2(*reinterpret_cast<__half2*>(&u2.x));
                    float2 b2 = __half22float2(*reinterpret_cast<__half2*>(&u2.y));
                    float2 a3 = __half22float2(*reinterpret_cast<__half2*>(&u3.x));
                    float2 b3 = __half22float2(*reinterpret_cast<__half2*>(&u3.y));
                    acc[0] += a0.x * w0 + a1.x * w1 + a2.x * w2 + a3.x * w3;
                    acc[1] += a0.y * w0 + a1.y * w1 + a2.y * w2 + a3.y * w3;
                    acc[2] += b0.x * w0 + b1.x * w1 + b2.x * w2 + b3.x * w3;
                    acc[3] += b0.y * w0 + b1.y * w1 + b2.y * w2 + b3.y * w3;
                } else {
                    unsigned u0 = *(const unsigned*)(hp + (size_t)s0 * K + lane * 2);
                    unsigned u1 = *(const unsigned*)(hp + (size_t)s1 * K + lane * 2);
                    unsigned u2 = *(const unsigned*)(hp + (size_t)s2 * K + lane * 2);
                    unsigned u3 = *(const unsigned*)(hp + (size_t)s3 * K + lane * 2);
                    float2 a0 = __half22float2(*reinterpret_cast<__half2*>(&u0));
                    float2 a1 = __half22float2(*reinterpret_cast<__half2*>(&u1));
                    float2 a2 = __half22float2(*reinterpret_cast<__half2*>(&u2));
                    float2 a3 = __half22float2(*reinterpret_cast<__half2*>(&u3));
                    acc[0] += a0.x * w0 + a1.x * w1 + a2.x * w2 + a3.x * w3;
                    acc[1] += a0.y * w0 + a1.y * w1 + a2.y * w2 + a3.y * w3;
                }
            }
            for (; j < end; j++) {
                int s; float w; eunpack(g_edge[j], s, w);
                if (VPL == 4) {
                    uint2 u = *(const uint2*)(hp + (size_t)s * K + lane * 4);
                    float2 f0 = __half22float2(*reinterpret_cast<__half2*>(&u.x));
                    float2 f1 = __half22float2(*reinterpret_cast<__half2*>(&u.y));
                    acc[0] += f0.x * w; acc[1] += f0.y * w; acc[2] += f1.x * w; acc[3] += f1.y * w;
                } else {
                    unsigned u = *(const unsigned*)(hp + (size_t)s * K + lane * 2);
                    float2 f0 = __half22float2(*reinterpret_cast<__half2*>(&u));
                    acc[0] += f0.x * w; acc[1] += f0.y * w;
                }
            }
#pragma unroll
            for (int v = 0; v < VPL; v += 2) {
                __half2 hh = __floats2half2_rn(acc[v], acc[v + 1]);
                *(__half2*)&shA[lr * Kp + lane * VPL + v] = hh;
            }
        } else {
#pragma unroll
            for (int v = 0; v < VPL; v += 2)
                *(__half2*)&shA[lr * Kp + lane * VPL + v] = __floats2half2_rn(0.f, 0.f);
        }
    }
    __syncthreads();

    // ---- phase B: WMMA from smem ----
    {
        wmma::fragment<wmma::matrix_a, 16, 16, 16, __half, wmma::row_major> fa;
        wmma::fragment<wmma::matrix_b, 16, 16, 16, __half, wmma::row_major> fb;
        wmma::fragment<wmma::accumulator, 16, 16, 16, float> fc;
        wmma::fill_fragment(fc, 0.0f);
#pragma unroll
        for (int k = 0; k < K; k += 16) {
            wmma::load_matrix_sync(fa, shA + k, Kp);
            wmma::load_matrix_sync(fb, sW + k * Cp + wid * 16, Cp);
            wmma::mma_sync(fc, fa, fb, fc);
        }
        __syncthreads();  // all warps done reading sW before sC overwrite
        wmma::store_matrix_sync(sC + wid * 16, fc, Cp4, wmma::mem_row_major);
    }
    __syncthreads();

    // ---- epilogue: bias + relu (+ pool) from sC ----
    int tc = tid & 63, ty = tid >> 6;  // cols 2tc,2tc+1; rows ty*4..ty*4+3
    float2 bb = *(const float2*)&b[2 * tc];
    if (!POOL) {
#pragma unroll
        for (int r = 0; r < 4; r++) {
            int lr = ty * 4 + r;
            int row = row0 + lr;
            if (row < n) {
                float xv = sC[lr * Cp4 + 2 * tc] + bb.x;
                float yv = sC[lr * Cp4 + 2 * tc + 1] + bb.y;
                __half2 o = __floats2half2_rn(fmaxf(xv, 0.0f), fmaxf(yv, 0.0f));
                *(__half2*)&g_h1[(size_t)row * C + 2 * tc] = o;
            }
        }
    } else {
        int curg = -1;
        float rx = 0.0f, ry = 0.0f;
#pragma unroll
        for (int r = 0; r < 4; r++) {
            int lr = ty * 4 + r;
            int row = row0 + lr;
            if (row >= n) break;
            float xv = fmaxf(sC[lr * Cp4 + 2 * tc] + bb.x, 0.0f);
            float yv = fmaxf(sC[lr * Cp4 + 2 * tc + 1] + bb.y, 0.0f);
            int g = __ldg(&batch[row]);
            if (g != curg) {
                if (curg >= 0) {
                    atomicAdd(&g_psum[curg * 128 + 2 * tc], rx);
                    atomicAdd(&g_psum[curg * 128 + 2 * tc + 1], ry);
                }
                curg = g; rx = 0.0f; ry = 0.0f;
            }
            rx += xv; ry += yv;
        }
        if (curg >= 0) {
            atomicAdd(&g_psum[curg * 128 + 2 * tc], rx);
            atomicAdd(&g_psum[curg * 128 + 2 * tc + 1], ry);
        }
    }
}

// ---------------- MLP head ----------------
__global__ void k_fc(const float* __restrict__ Wf1, const float* __restrict__ bf1,
                     const float* __restrict__ Wf2, const float* __restrict__ bf2,
                     float* __restrict__ out) {
    int g = blockIdx.x;
    int t = threadIdx.x;  // 128
    __shared__ float p[128];
    __shared__ float f1[64];
    float inv = 1.0f / fmaxf(g_pcnt[g], 1.0f);
    p[t] = g_psum[g * 128 + t] * inv;
    __syncthreads();
    if (t < 64) {
        float acc = bf1[t];
#pragma unroll
        for (int k = 0; k < 128; k++) acc += p[k] * Wf1[k * 64 + t];
        f1[t] = fmaxf(acc, 0.0f);
    }
    __syncthreads();
    if (t < 10) {
        float acc = bf2[t];
#pragma unroll
        for (int k = 0; k < 64; k++) acc += f1[k] * Wf2[k * 10 + t];
        out[g * 10 + t] = acc;
    }
}

extern "C" void kernel_launch(void* const* d_in, const int* in_sizes, int n_in,
                              void* d_out, int out_size) {
    const float* x   = (const float*)d_in[0];
    const int* ei    = (const int*)d_in[1];
    const int* batch = (const int*)d_in[2];
    const float* W1  = (const float*)d_in[3];
    const float* b1  = (const float*)d_in[4];
    const float* W2  = (const float*)d_in[5];
    const float* b2  = (const float*)d_in[6];
    const float* W3  = (const float*)d_in[7];
    const float* b3  = (const float*)d_in[8];
    const float* Wf1 = (const float*)d_in[9];
    const float* bf1 = (const float*)d_in[10];
    const float* Wf2 = (const float*)d_in[11];
    const float* bf2 = (const float*)d_in[12];
    float* out = (float*)d_out;

    int N = in_sizes[0] / 3;
    int E = in_sizes[1] / 2;
    const int* src = ei;
    const int* dst = ei + E;
    int NB = (N + SCAN_B - 1) / SCAN_B;  // <= 49

    // zero + weight fp16 conversion + single-wave CSR builder
    k_zero<<<(N + 255) / 256, 256>>>(W2, W3, N);
    k_prep<<<NB, SCAN_B>>>(src, dst, batch, N, E);

    // Fused layers
    k_layer1<<<(N + 63) / 64, 256>>>(x, W1, b1, N);
    k_layer<64, 2, false><<<(N + 15) / 16, 256>>>(b2, batch, N);
    k_layer<128, 4, true><<<(N + 15) / 16, 256>>>(b3, batch, N);

    // Head
    k_fc<<<GRAPHS, 128>>>(Wf1, bf1, Wf2, bf2, out);
}

// round 14
// speedup vs baseline: 1.3886x; 1.0256x over previous
#include <cuda_runtime.h>
#include <cuda_bf16.h>
#include <cuda_fp16.h>
#include <mma.h>

using namespace nvcuda;

#define NMAX 50000
#define EMAX 800000
#define GRAPHS 64
#define SCAN_B 1024

// ---------------- device scratch (allocation-free rule) ----------------
static __device__ __half g_h0[NMAX * 64];   // layer-1 output, fp16
static __device__ __half g_h1[NMAX * 128];  // layer-2 output, fp16
static __device__ __half g_w2h[64 * 128];   // W2 in fp16
static __device__ __half g_w3h[128 * 128];  // W3 in fp16
static __device__ float4 g_x4[NMAX];        // x padded to float4
static __device__ float g_dinv[NMAX];
static __device__ int   g_cnt[NMAX];
static __device__ int   g_rowptr[NMAX + 1];
static __device__ int   g_cursor[NMAX];
static __device__ int   g_bsum[64];
static __device__ int   g_sync;             // spin barrier (zeroed by k_zero)
static __device__ unsigned long long g_edge[EMAX];  // packed {norm<<32 | src}
static __device__ float g_psum[GRAPHS * 128];
static __device__ float g_pcnt[GRAPHS];

typedef unsigned long long ull;

// unpack edge record
__device__ __forceinline__ void eunpack(ull r, int& s, float& w) {
    s = (int)(unsigned)r;
    w = __uint_as_float((unsigned)(r >> 32));
}

// ---------------- prep ----------------
__global__ void k_zero(const float* __restrict__ W2, const float* __restrict__ W3,
                       const float* __restrict__ x, int n) {
    int i = blockIdx.x * blockDim.x + threadIdx.x;
    if (i < n) {
        g_cnt[i] = 0;
        g_x4[i] = make_float4(x[i * 3], x[i * 3 + 1], x[i * 3 + 2], 0.0f);
    }
    if (i < GRAPHS * 128) g_psum[i] = 0.0f;
    if (i < GRAPHS) g_pcnt[i] = 0.0f;
    if (i == 0) g_sync = 0;
    if (i < 64 * 128) g_w2h[i] = __float2half(W2[i]);
    if (i < 128 * 128) g_w3h[i] = __float2half(W3[i]);
}

// Single-wave CSR builder: count -> scan -> fill, with spin grid barriers.
__global__ void __launch_bounds__(1024) k_prep(const int* __restrict__ src,
                                               const int* __restrict__ dst,
                                               const int* __restrict__ batch,
                                               int n, int E) {
    __shared__ int swarp[32];
    __shared__ int pref[64];
    __shared__ int wtot;
    int t = threadIdx.x;
    int lane = t & 31, wid = t >> 5;
    int nb = gridDim.x;
    int gtid = blockIdx.x * SCAN_B + t;
    int nthr = nb * SCAN_B;

    // ---- phase 1: histograms ----
    for (int e = gtid; e < E; e += nthr) atomicAdd(&g_cnt[dst[e]], 1);
    for (int i = gtid; i < n; i += nthr) atomicAdd(&g_pcnt[batch[i]], 1.0f);

    __threadfence();
    __syncthreads();
    if (t == 0) {
        atomicAdd(&g_sync, 1);
        while (atomicAdd(&g_sync, 0) < nb) { }
    }
    __syncthreads();

    // ---- phase 2: local scan + dinv ----
    int i = gtid;
    int v = (i < n) ? g_cnt[i] : 0;
    if (i < n) g_dinv[i] = rsqrtf((float)v + 1.0f);
    int incl = v;
#pragma unroll
    for (int off = 1; off < 32; off <<= 1) {
        int y = __shfl_up_sync(0xffffffffu, incl, off);
        if (lane >= off) incl += y;
    }
    if (lane == 31) swarp[wid] = incl;
    __syncthreads();
    if (wid == 0) {
        int w = swarp[lane];
#pragma unroll
        for (int off = 1; off < 32; off <<= 1) {
            int y = __shfl_up_sync(0xffffffffu, w, off);
            if (lane >= off) w += y;
        }
        swarp[lane] = w;
    }
    __syncthreads();
    int excl = incl - v + ((wid > 0) ? swarp[wid - 1] : 0);
    if (t == SCAN_B - 1) g_bsum[blockIdx.x] = excl + v;

    __threadfence();
    __syncthreads();
    if (t == 0) {
        atomicAdd(&g_sync, 1);
        while (atomicAdd(&g_sync, 0) < 2 * nb) { }
    }
    __syncthreads();

    // ---- phase 3: prefix block totals, write rowptr/cursor ----
    if (t < 64) {
        int bv = (t < nb) ? g_bsum[t] : 0;
        int binc = bv;
#pragma unroll
        for (int off = 1; off < 32; off <<= 1) {
            int y = __shfl_up_sync(0xffffffffu, binc, off);
            if (lane >= off) binc += y;
        }
        pref[t] = binc - bv;
        if (t == 31) wtot = binc;
    }
    __syncthreads();
    if (t >= 32 && t < 64) pref[t] += wtot;
    __syncthreads();
    if (i < n) {
        int rp = excl + pref[blockIdx.x];
        g_rowptr[i] = rp;
        g_cursor[i] = rp;
    }
    if (gtid == 0) g_rowptr[n] = E;

    __threadfence();
    __syncthreads();
    if (t == 0) {
        atomicAdd(&g_sync, 1);
        while (atomicAdd(&g_sync, 0) < 3 * nb) { }
    }
    __syncthreads();

    // ---- phase 4: fill packed edge records ----
    for (int e = gtid; e < E; e += nthr) {
        int s = src[e], d = dst[e];
        int pos = atomicAdd(&g_cursor[d], 1);
        float nm = g_dinv[s] * g_dinv[d];
        g_edge[pos] = ((ull)__float_as_uint(nm) << 32) | (unsigned)s;
    }
}

// ---------------- Layer 1 fused: agg(C=3) + 3->64 GEMM + relu -> g_h0 -------
__global__ void __launch_bounds__(256) k_layer1(const float* __restrict__ W,
                                                const float* __restrict__ b, int n) {
    const int NPB = 64;
    __shared__ float sa[NPB][3];
    __shared__ float sW[192];
    __shared__ float sb[64];
    int tid = threadIdx.x, wid = tid >> 5, lane = tid & 31;
    int node0 = blockIdx.x * NPB;
    if (tid < 192) sW[tid] = W[tid];
    if (tid < 64) sb[tid] = b[tid];

    for (int k = 0; k < NPB; k += 8) {
        int lr = k + wid;
        int i = node0 + lr;
        if (i < n) {
            int beg = g_rowptr[i], end = g_rowptr[i + 1];
            float a0 = 0.f, a1 = 0.f, a2 = 0.f;
            for (int j = beg + lane; j < end; j += 32) {
                int s; float w; eunpack(g_edge[j], s, w);
                float4 xv = g_x4[s];
                a0 += xv.x * w;
                a1 += xv.y * w;
                a2 += xv.z * w;
            }
#pragma unroll
            for (int off = 16; off > 0; off >>= 1) {
                a0 += __shfl_down_sync(0xffffffffu, a0, off);
                a1 += __shfl_down_sync(0xffffffffu, a1, off);
                a2 += __shfl_down_sync(0xffffffffu, a2, off);
            }
            if (lane == 0) {
                float di = g_dinv[i], sw = di * di;
                float4 xv = g_x4[i];
                sa[lr][0] = a0 + xv.x * sw;
                sa[lr][1] = a1 + xv.y * sw;
                sa[lr][2] = a2 + xv.z * sw;
            }
        }
    }
    __syncthreads();

    int tc = tid & 63, ty = tid >> 6;
    float w0 = sW[tc], w1 = sW[64 + tc], w2 = sW[128 + tc], bb = sb[tc];
#pragma unroll 4
    for (int r = 0; r < 16; r++) {
        int lr = ty * 16 + r;
        int row = node0 + lr;
        if (row >= n) break;
        float v = bb + sa[lr][0] * w0 + sa[lr][1] * w1 + sa[lr][2] * w2;
        g_h0[row * 64 + tc] = __float2half(fmaxf(v, 0.0f));
    }
}

// ---------------- Fused layer: agg(K) + KxC GEMM via WMMA (+relu) ----------
// K in {64,128}, C=128. Block: 256 thr, 32 nodes.
// Phase A: warp aggregates 4 nodes (fp32 accum), stores fp16 to padded shA.
// W staged once per block into padded smem [K][136] (coalesced uint4 copy);
// ROWS=32 halves staging traffic vs ROWS=16 and reuses each fb fragment 2x.
// Phase B: 8 warps x two 16x16 wmma tiles (rows 0-15 and 16-31).
// sC (fp32, padded [32][132]) ALIASES sW (dead after mma).
template <int K, int VPL, bool POOL>
__global__ void __launch_bounds__(256) k_layer(const float* __restrict__ b,
                                               const int* __restrict__ batch, int n) {
    const int C = 128, ROWS = 32;
    const int Kp = K + 8;      // half elems; row stride (K+8)*2 bytes, mult of 16
    const int Cp = 136;        // half elems; 272B row stride
    const int Cp4 = 132;       // float elems; 528B row stride
    __shared__ __align__(16) __half shA[ROWS * Kp];
    __shared__ __align__(16) __half sW[K * Cp];   // reused as sC after mma
    float* sC = (float*)sW;    // 32*132*4 = 16896B <= K*Cp*2 (17408 @K=64)

    int tid = threadIdx.x, wid = tid >> 5, lane = tid & 31;
    int row0 = blockIdx.x * ROWS;
    const __half* __restrict__ hp = (K == 64) ? g_h0 : g_h1;
    const __half* __restrict__ Wh = (K == 64) ? g_w2h : g_w3h;

    // ---- stage W into padded smem (K rows x 16 uint4 each) ----
    {
        const uint4* Wg = (const uint4*)Wh;
        for (int idx = tid; idx < K * 16; idx += 256) {
            int r = idx >> 4, c = idx & 15;
            ((uint4*)(sW + r * Cp))[c] = Wg[r * 16 + c];
        }
    }

    // ---- phase A: aggregation (4 nodes per warp) ----
#pragma unroll
    for (int rr = 0; rr < 4; rr++) {
        int lr = wid * 4 + rr;
        int i = row0 + lr;
        if (i < n) {
            int beg = g_rowptr[i], end = g_rowptr[i + 1];
            float di = g_dinv[i], sw = di * di;
            float acc[VPL];
            if (VPL == 4) {
                uint2 u = *(const uint2*)(hp + (size_t)i * K + lane * 4);
                float2 f0 = __half22float2(*reinterpret_cast<__half2*>(&u.x));
                float2 f1 = __half22float2(*reinterpret_cast<__half2*>(&u.y));
                acc[0] = f0.x * sw; acc[1] = f0.y * sw; acc[2] = f1.x * sw; acc[3] = f1.y * sw;
            } else {
                unsigned u = *(const unsigned*)(hp + (size_t)i * K + lane * 2);
                float2 f0 = __half22float2(*reinterpret_cast<__half2*>(&u));
                acc[0] = f0.x * sw; acc[1] = f0.y * sw;
            }
            int j = beg;
            for (; j + 4 <= end; j += 4) {
                int s0, s1, s2, s3; float w0, w1, w2, w3;
                eunpack(g_edge[j], s0, w0);
                eunpack(g_edge[j + 1], s1, w1);
                eunpack(g_edge[j + 2], s2, w2);
                eunpack(g_edge[j + 3], s3, w3);
                if (VPL == 4) {
                    uint2 u0 = *(const uint2*)(hp + (size_t)s0 * K + lane * 4);
                    uint2 u1 = *(const uint2*)(hp + (size_t)s1 * K + lane * 4);
                    uint2 u2 = *(const uint2*)(hp + (size_t)s2 * K + lane * 4);
                    uint2 u3 = *(const uint2*)(hp + (size_t)s3 * K + lane * 4);
                    float2 a0 = __half22float2(*reinterpret_cast<__half2*>(&u0.x));
                    float2 b0 = __half22float2(*reinterpret_cast<__half2*>(&u0.y));
                    float2 a1 = __half22float2(*reinterpret_cast<__half2*>(&u1.x));
                    float2 b1 = __half22float2(*reinterpret_cast<__half2*>(&u1.y));
                    float2 a2 = __half22float2(*reinterpret_cast<__half2*>(&u2.x));
                    float2 b2 = __half22float2(*reinterpret_cast<__half2*>(&u2.y));
                    float2 a3 = __half22float2(*reinterpret_cast<__half2*>(&u3.x));
                    float2 b3 = __half22float2(*reinterpret_cast<__half2*>(&u3.y));
                    acc[0] += a0.x * w0 + a1.x * w1 + a2.x * w2 + a3.x * w3;
                    acc[1] += a0.y * w0 + a1.y * w1 + a2.y * w2 + a3.y * w3;
                    acc[2] += b0.x * w0 + b1.x * w1 + b2.x * w2 + b3.x * w3;
                    acc[3] += b0.y * w0 + b1.y * w1 + b2.y * w2 + b3.y * w3;
                } else {
                    unsigned u0 = *(const unsigned*)(hp + (size_t)s0 * K + lane * 2);
                    unsigned u1 = *(const unsigned*)(hp + (size_t)s1 * K + lane * 2);
                    unsigned u2 = *(const unsigned*)(hp + (size_t)s2 * K + lane * 2);
                    unsigned u3 = *(const unsigned*)(hp + (size_t)s3 * K + lane * 2);
                    float2 a0 = __half22float2(*reinterpret_cast<__half2*>(&u0));
                    float2 a1 = __half22float2(*reinterpret_cast<__half2*>(&u1));
                    float2 a2 = __half22float2(*reinterpret_cast<__half2*>(&u2));
                    float2 a3 = __half22float2(*reinterpret_cast<__half2*>(&u3));
                    acc[0] += a0.x * w0 + a1.x * w1 + a2.x * w2 + a3.x * w3;
                    acc[1] += a0.y * w0 + a1.y * w1 + a2.y * w2 + a3.y * w3;
                }
            }
            for (; j < end; j++) {
                int s; float w; eunpack(g_edge[j], s, w);
                if (VPL == 4) {
                    uint2 u = *(const uint2*)(hp + (size_t)s * K + lane * 4);
                    float2 f0 = __half22float2(*reinterpret_cast<__half2*>(&u.x));
                    float2 f1 = __half22float2(*reinterpret_cast<__half2*>(&u.y));
                    acc[0] += f0.x * w; acc[1] += f0.y * w; acc[2] += f1.x * w; acc[3] += f1.y * w;
                } else {
                    unsigned u = *(const unsigned*)(hp + (size_t)s * K + lane * 2);
                    float2 f0 = __half22float2(*reinterpret_cast<__half2*>(&u));
                    acc[0] += f0.x * w; acc[1] += f0.y * w;
                }
            }
#pragma unroll
            for (int v = 0; v < VPL; v += 2) {
                __half2 hh = __floats2half2_rn(acc[v], acc[v + 1]);
                *(__half2*)&shA[lr * Kp + lane * VPL + v] = hh;
            }
        } else {
#pragma unroll
            for (int v = 0; v < VPL; v += 2)
                *(__half2*)&shA[lr * Kp + lane * VPL + v] = __floats2half2_rn(0.f, 0.f);
        }
    }
    __syncthreads();

    // ---- phase B: WMMA from smem (2 row-tiles per warp, fb reused) ----
    {
        wmma::fragment<wmma::matrix_a, 16, 16, 16, __half, wmma::row_major> fa0, fa1;
        wmma::fragment<wmma::matrix_b, 16, 16, 16, __half, wmma::row_major> fb;
        wmma::fragment<wmma::accumulator, 16, 16, 16, float> fc0, fc1;
        wmma::fill_fragment(fc0, 0.0f);
        wmma::fill_fragment(fc1, 0.0f);
#pragma unroll
        for (int k = 0; k < K; k += 16) {
            wmma::load_matrix_sync(fa0, shA + k, Kp);
            wmma::load_matrix_sync(fa1, shA + 16 * Kp + k, Kp);
            wmma::load_matrix_sync(fb, sW + k * Cp + wid * 16, Cp);
            wmma::mma_sync(fc0, fa0, fb, fc0);
            wmma::mma_sync(fc1, fa1, fb, fc1);
        }
        __syncthreads();  // all warps done reading sW before sC overwrite
        wmma::store_matrix_sync(sC + wid * 16, fc0, Cp4, wmma::mem_row_major);
        wmma::store_matrix_sync(sC + 16 * Cp4 + wid * 16, fc1, Cp4, wmma::mem_row_major);
    }
    __syncthreads();

    // ---- epilogue: bias + relu (+ pool) from sC ----
    int tc = tid & 63, ty = tid >> 6;  // cols 2tc,2tc+1; rows ty*8..ty*8+7
    float2 bb = *(const float2*)&b[2 * tc];
    if (!POOL) {
#pragma unroll
        for (int r = 0; r < 8; r++) {
            int lr = ty * 8 + r;
            int row = row0 + lr;
            if (row < n) {
                float xv = sC[lr * Cp4 + 2 * tc] + bb.x;
                float yv = sC[lr * Cp4 + 2 * tc + 1] + bb.y;
                __half2 o = __floats2half2_rn(fmaxf(xv, 0.0f), fmaxf(yv, 0.0f));
                *(__half2*)&g_h1[(size_t)row * C + 2 * tc] = o;
            }
        }
    } else {
        int curg = -1;
        float rx = 0.0f, ry = 0.0f;
#pragma unroll
        for (int r = 0; r < 8; r++) {
            int lr = ty * 8 + r;
            int row = row0 + lr;
            if (row >= n) break;
            float xv = fmaxf(sC[lr * Cp4 + 2 * tc] + bb.x, 0.0f);
            float yv = fmaxf(sC[lr * Cp4 + 2 * tc + 1] + bb.y, 0.0f);
            int g = __ldg(&batch[row]);
            if (g != curg) {
                if (curg >= 0) {
                    atomicAdd(&g_psum[curg * 128 + 2 * tc], rx);
                    atomicAdd(&g_psum[curg * 128 + 2 * tc + 1], ry);
                }
                curg = g; rx = 0.0f; ry = 0.0f;
            }
            rx += xv; ry += yv;
        }
        if (curg >= 0) {
            atomicAdd(&g_psum[curg * 128 + 2 * tc], rx);
            atomicAdd(&g_psum[curg * 128 + 2 * tc + 1], ry);
        }
    }
}

// ---------------- MLP head ----------------
__global__ void k_fc(const float* __restrict__ Wf1, const float* __restrict__ bf1,
                     const float* __restrict__ Wf2, const float* __restrict__ bf2,
                     float* __restrict__ out) {
    int g = blockIdx.x;
    int t = threadIdx.x;  // 128
    __shared__ float p[128];
    __shared__ float f1[64];
    float inv = 1.0f / fmaxf(g_pcnt[g], 1.0f);
    p[t] = g_psum[g * 128 + t] * inv;
    __syncthreads();
    if (t < 64) {
        float acc = bf1[t];
#pragma unroll
        for (int k = 0; k < 128; k++) acc += p[k] * Wf1[k * 64 + t];
        f1[t] = fmaxf(acc, 0.0f);
    }
    __syncthreads();
    if (t < 10) {
        float acc = bf2[t];
#pragma unroll
        for (int k = 0; k < 64; k++) acc += f1[k] * Wf2[k * 10 + t];
        out[g * 10 + t] = acc;
    }
}

extern "C" void kernel_launch(void* const* d_in, const int* in_sizes, int n_in,
                              void* d_out, int out_size) {
    const float* x   = (const float*)d_in[0];
    const int* ei    = (const int*)d_in[1];
    const int* batch = (const int*)d_in[2];
    const float* W1  = (const float*)d_in[3];
    const float* b1  = (const float*)d_in[4];
    const float* W2  = (const float*)d_in[5];
    const float* b2  = (const float*)d_in[6];
    const float* W3  = (const float*)d_in[7];
    const float* b3  = (const float*)d_in[8];
    const float* Wf1 = (const float*)d_in[9];
    const float* bf1 = (const float*)d_in[10];
    const float* Wf2 = (const float*)d_in[11];
    const float* bf2 = (const float*)d_in[12];
    float* out = (float*)d_out;

    int N = in_sizes[0] / 3;
    int E = in_sizes[1] / 2;
    const int* src = ei;
    const int* dst = ei + E;
    int NB = (N + SCAN_B - 1) / SCAN_B;  // <= 49

    // zero + weight fp16 conversion + x padding + single-wave CSR builder
    k_zero<<<(N + 255) / 256, 256>>>(W2, W3, x, N);
    k_prep<<<NB, SCAN_B>>>(src, dst, batch, N, E);

    // Fused layers
    k_layer1<<<(N + 63) / 64, 256>>>(W1, b1, N);
    k_layer<64, 2, false><<<(N + 31) / 32, 256>>>(b2, batch, N);
    k_layer<128, 4, true><<<(N + 31) / 32, 256>>>(b3, batch, N);

    // Head
    k_fc<<<GRAPHS, 128>>>(Wf1, bf1, Wf2, bf2, out);
}

// round 15
// speedup vs baseline: 1.3912x; 1.0019x over previous
#include <cuda_runtime.h>
#include <cuda_bf16.h>
#include <cuda_fp16.h>
#include <mma.h>

using namespace nvcuda;

#define NMAX 50000
#define EMAX 800000
#define GRAPHS 64
#define SCAN_B 1024

// ---------------- device scratch (allocation-free rule) ----------------
static __device__ __half g_h0[NMAX * 64];   // layer-1 output, fp16
static __device__ __half g_h1[NMAX * 128];  // layer-2 output, fp16
static __device__ __half g_w2h[64 * 128];   // W2 in fp16
static __device__ __half g_w3h[128 * 128];  // W3 in fp16
static __device__ float4 g_x4[NMAX];        // x padded to float4
static __device__ float g_dinv[NMAX];
static __device__ int   g_cnt[NMAX];
static __device__ int   g_rowptr[NMAX + 1];
static __device__ int   g_cursor[NMAX];
static __device__ int   g_bsum[64];
static __device__ int   g_sync;             // zero-init at load; self-reset per launch
static __device__ unsigned long long g_edge[EMAX];  // packed {norm<<32 | src}
static __device__ float g_psum[GRAPHS * 128];
static __device__ float g_pcnt[GRAPHS];

typedef unsigned long long ull;

__device__ __forceinline__ void eunpack(ull r, int& s, float& w) {
    s = (int)(unsigned)r;
    w = __uint_as_float((unsigned)(r >> 32));
}

// spin grid barrier helper (t==0 arrives; all threads blocked by syncthreads)
__device__ __forceinline__ void grid_bar(int t, int target) {
    __threadfence();
    __syncthreads();
    if (t == 0) {
        atomicAdd(&g_sync, 1);
        while (atomicAdd(&g_sync, 0) < target) { }
    }
    __syncthreads();
}

// Single-wave prep: zero/convert -> count -> scan -> fill, spin grid barriers.
// gridDim.x <= 49 blocks of 1024: single wave on 148 SMs, deadlock-free.
__global__ void __launch_bounds__(1024) k_prep(const int* __restrict__ src,
                                               const int* __restrict__ dst,
                                               const int* __restrict__ batch,
                                               const float* __restrict__ W2,
                                               const float* __restrict__ W3,
                                               const float* __restrict__ x,
                                               int n, int E) {
    __shared__ int swarp[32];
    __shared__ int pref[64];
    __shared__ int wtot;
    int t = threadIdx.x;
    int lane = t & 31, wid = t >> 5;
    int nb = gridDim.x;
    int gtid = blockIdx.x * SCAN_B + t;
    int nthr = nb * SCAN_B;

    // ---- phase 0: zero + fp16 weight conversion + x padding ----
    for (int i = gtid; i < n; i += nthr) {
        g_cnt[i] = 0;
        g_x4[i] = make_float4(x[i * 3], x[i * 3 + 1], x[i * 3 + 2], 0.0f);
    }
    if (gtid < GRAPHS * 128) g_psum[gtid] = 0.0f;
    if (gtid < GRAPHS) g_pcnt[gtid] = 0.0f;
    if (gtid < 64 * 128) g_w2h[gtid] = __float2half(W2[gtid]);
    if (gtid < 128 * 128) g_w3h[gtid] = __float2half(W3[gtid]);
    grid_bar(t, nb);

    // ---- phase 1: histograms ----
    for (int e = gtid; e < E; e += nthr) atomicAdd(&g_cnt[dst[e]], 1);
    for (int i = gtid; i < n; i += nthr) atomicAdd(&g_pcnt[batch[i]], 1.0f);
    grid_bar(t, 2 * nb);

    // ---- phase 2: local scan + dinv ----
    int i = gtid;
    int v = (i < n) ? g_cnt[i] : 0;
    if (i < n) g_dinv[i] = rsqrtf((float)v + 1.0f);
    int incl = v;
#pragma unroll
    for (int off = 1; off < 32; off <<= 1) {
        int y = __shfl_up_sync(0xffffffffu, incl, off);
        if (lane >= off) incl += y;
    }
    if (lane == 31) swarp[wid] = incl;
    __syncthreads();
    if (wid == 0) {
        int w = swarp[lane];
#pragma unroll
        for (int off = 1; off < 32; off <<= 1) {
            int y = __shfl_up_sync(0xffffffffu, w, off);
            if (lane >= off) w += y;
        }
        swarp[lane] = w;
    }
    __syncthreads();
    int excl = incl - v + ((wid > 0) ? swarp[wid - 1] : 0);
    if (t == SCAN_B - 1) g_bsum[blockIdx.x] = excl + v;
    grid_bar(t, 3 * nb);

    // ---- phase 3: prefix block totals, write rowptr/cursor ----
    if (t < 64) {
        int bv = (t < nb) ? g_bsum[t] : 0;
        int binc = bv;
#pragma unroll
        for (int off = 1; off < 32; off <<= 1) {
            int y = __shfl_up_sync(0xffffffffu, binc, off);
            if (lane >= off) binc += y;
        }
        pref[t] = binc - bv;
        if (t == 31) wtot = binc;
    }
    __syncthreads();
    if (t >= 32 && t < 64) pref[t] += wtot;
    __syncthreads();
    if (i < n) {
        int rp = excl + pref[blockIdx.x];
        g_rowptr[i] = rp;
        g_cursor[i] = rp;
    }
    if (gtid == 0) g_rowptr[n] = E;
    grid_bar(t, 4 * nb);

    // ---- phase 4: fill packed edge records ----
    for (int e = gtid; e < E; e += nthr) {
        int s = src[e], d = dst[e];
        int pos = atomicAdd(&g_cursor[d], 1);
        float nm = g_dinv[s] * g_dinv[d];
        g_edge[pos] = ((ull)__float_as_uint(nm) << 32) | (unsigned)s;
    }

    // ---- final: self-reset g_sync (no one waits; last finisher resets) ----
    __threadfence();
    __syncthreads();
    if (t == 0) {
        int tk = atomicAdd(&g_sync, 1);
        if (tk == 5 * nb - 1) g_sync = 0;
    }
}

// ---------------- Layer 1 fused: agg(C=3) + 3->64 GEMM + relu -> g_h0 -------
__global__ void __launch_bounds__(256) k_layer1(const float* __restrict__ W,
                                                const float* __restrict__ b, int n) {
    const int NPB = 64;
    __shared__ float sa[NPB][3];
    __shared__ float sW[192];
    __shared__ float sb[64];
    int tid = threadIdx.x, wid = tid >> 5, lane = tid & 31;
    int node0 = blockIdx.x * NPB;
    if (tid < 192) sW[tid] = W[tid];
    if (tid < 64) sb[tid] = b[tid];

    for (int k = 0; k < NPB; k += 8) {
        int lr = k + wid;
        int i = node0 + lr;
        if (i < n) {
            int beg = g_rowptr[i], end = g_rowptr[i + 1];
            float a0 = 0.f, a1 = 0.f, a2 = 0.f;
            for (int j = beg + lane; j < end; j += 32) {
                int s; float w; eunpack(g_edge[j], s, w);
                float4 xv = g_x4[s];
                a0 += xv.x * w;
                a1 += xv.y * w;
                a2 += xv.z * w;
            }
#pragma unroll
            for (int off = 16; off > 0; off >>= 1) {
                a0 += __shfl_down_sync(0xffffffffu, a0, off);
                a1 += __shfl_down_sync(0xffffffffu, a1, off);
                a2 += __shfl_down_sync(0xffffffffu, a2, off);
            }
            if (lane == 0) {
                float di = g_dinv[i], sw = di * di;
                float4 xv = g_x4[i];
                sa[lr][0] = a0 + xv.x * sw;
                sa[lr][1] = a1 + xv.y * sw;
                sa[lr][2] = a2 + xv.z * sw;
            }
        }
    }
    __syncthreads();

    int tc = tid & 63, ty = tid >> 6;
    float w0 = sW[tc], w1 = sW[64 + tc], w2 = sW[128 + tc], bb = sb[tc];
#pragma unroll 4
    for (int r = 0; r < 16; r++) {
        int lr = ty * 16 + r;
        int row = node0 + lr;
        if (row >= n) break;
        float v = bb + sa[lr][0] * w0 + sa[lr][1] * w1 + sa[lr][2] * w2;
        g_h0[row * 64 + tc] = __float2half(fmaxf(v, 0.0f));
    }
}

// ---------------- Fused layer: agg(K) + KxC GEMM via WMMA (+relu) ----------
// K in {64,128}, C=128. Block: 256 thr, ROWS nodes (16 for K=64, 32 for K=128
// — per-K measured optimum).
// Phase A: warp aggregates ROWS/8 nodes (fp32 accum), stores fp16 to padded shA.
// W staged once per block into padded smem [K][136] (coalesced uint4 copy).
// Phase B: 8 warps x (ROWS/16) 16x16 wmma tiles. sC aliases sW (dead after mma).
template <int K, int VPL, int ROWS, bool POOL>
__global__ void __launch_bounds__(256) k_layer(const float* __restrict__ b,
                                               const int* __restrict__ batch, int n) {
    const int C = 128;
    const int Kp = K + 8;      // half elems; row stride mult of 16B
    const int Cp = 136;        // half elems; 272B row stride
    const int Cp4 = 132;       // float elems; 528B row stride
    const int NPW = ROWS / 8;  // nodes per warp in phase A
    const int RT = ROWS / 16;  // row tiles in phase B
    const int RPE = ROWS / 4;  // rows per ty group in epilogue
    __shared__ __align__(16) __half shA[ROWS * Kp];
    __shared__ __align__(16) __half sW[K * Cp];   // reused as sC after mma
    float* sC = (float*)sW;    // ROWS*Cp4*4 <= K*Cp*2 (8448<=17408 / 16896<=34816)

    int tid = threadIdx.x, wid = tid >> 5, lane = tid & 31;
    int row0 = blockIdx.x * ROWS;
    const __half* __restrict__ hp = (K == 64) ? g_h0 : g_h1;
    const __half* __restrict__ Wh = (K == 64) ? g_w2h : g_w3h;

    // ---- stage W into padded smem (K rows x 16 uint4 each) ----
    {
        const uint4* Wg = (const uint4*)Wh;
        for (int idx = tid; idx < K * 16; idx += 256) {
            int r = idx >> 4, c = idx & 15;
            ((uint4*)(sW + r * Cp))[c] = Wg[r * 16 + c];
        }
    }

    // ---- phase A: aggregation ----
#pragma unroll
    for (int rr = 0; rr < NPW; rr++) {
        int lr = wid * NPW + rr;
        int i = row0 + lr;
        if (i < n) {
            int beg = g_rowptr[i], end = g_rowptr[i + 1];
            float di = g_dinv[i], sw = di * di;
            float acc[VPL];
            if (VPL == 4) {
                uint2 u = *(const uint2*)(hp + (size_t)i * K + lane * 4);
                float2 f0 = __half22float2(*reinterpret_cast<__half2*>(&u.x));
                float2 f1 = __half22float2(*reinterpret_cast<__half2*>(&u.y));
                acc[0] = f0.x * sw; acc[1] = f0.y * sw; acc[2] = f1.x * sw; acc[3] = f1.y * sw;
            } else {
                unsigned u = *(const unsigned*)(hp + (size_t)i * K + lane * 2);
                float2 f0 = __half22float2(*reinterpret_cast<__half2*>(&u));
                acc[0] = f0.x * sw; acc[1] = f0.y * sw;
            }
            int j = beg;
            for (; j + 4 <= end; j += 4) {
                int s0, s1, s2, s3; float w0, w1, w2, w3;
                eunpack(g_edge[j], s0, w0);
                eunpack(g_edge[j + 1], s1, w1);
                eunpack(g_edge[j + 2], s2, w2);
                eunpack(g_edge[j + 3], s3, w3);
                if (VPL == 4) {
                    uint2 u0 = *(const uint2*)(hp + (size_t)s0 * K + lane * 4);
                    uint2 u1 = *(const uint2*)(hp + (size_t)s1 * K + lane * 4);
                    uint2 u2 = *(const uint2*)(hp + (size_t)s2 * K + lane * 4);
                    uint2 u3 = *(const uint2*)(hp + (size_t)s3 * K + lane * 4);
                    float2 a0 = __half22float2(*reinterpret_cast<__half2*>(&u0.x));
                    float2 b0 = __half22float2(*reinterpret_cast<__half2*>(&u0.y));
                    float2 a1 = __half22float2(*reinterpret_cast<__half2*>(&u1.x));
                    float2 b1 = __half22float2(*reinterpret_cast<__half2*>(&u1.y));
                    float2 a2 = __half22float2(*reinterpret_cast<__half2*>(&u2.x));
                    float2 b2 = __half22float2(*reinterpret_cast<__half2*>(&u2.y));
                    float2 a3 = __half22float2(*reinterpret_cast<__half2*>(&u3.x));
                    float2 b3 = __half22float2(*reinterpret_cast<__half2*>(&u3.y));
                    acc[0] += a0.x * w0 + a1.x * w1 + a2.x * w2 + a3.x * w3;
                    acc[1] += a0.y * w0 + a1.y * w1 + a2.y * w2 + a3.y * w3;
                    acc[2] += b0.x * w0 + b1.x * w1 + b2.x * w2 + b3.x * w3;
                    acc[3] += b0.y * w0 + b1.y * w1 + b2.y * w2 + b3.y * w3;
                } else {
                    unsigned u0 = *(const unsigned*)(hp + (size_t)s0 * K + lane * 2);
                    unsigned u1 = *(const unsigned*)(hp + (size_t)s1 * K + lane * 2);
                    unsigned u2 = *(const unsigned*)(hp + (size_t)s2 * K + lane * 2);
                    unsigned u3 = *(const unsigned*)(hp + (size_t)s3 * K + lane * 2);
                    float2 a0 = __half22float2(*reinterpret_cast<__half2*>(&u0));
                    float2 a1 = __half22float2(*reinterpret_cast<__half2*>(&u1));
                    float2 a2 = __half22float2(*reinterpret_cast<__half2*>(&u2));
                    float2 a3 = __half22float2(*reinterpret_cast<__half2*>(&u3));
                    acc[0] += a0.x * w0 + a1.x * w1 + a2.x * w2 + a3.x * w3;
                    acc[1] += a0.y * w0 + a1.y * w1 + a2.y * w2 + a3.y * w3;
                }
            }
            for (; j < end; j++) {
                int s; float w; eunpack(g_edge[j], s, w);
                if (VPL == 4) {
                    uint2 u = *(const uint2*)(hp + (size_t)s * K + lane * 4);
                    float2 f0 = __half22float2(*reinterpret_cast<__half2*>(&u.x));
                    float2 f1 = __half22float2(*reinterpret_cast<__half2*>(&u.y));
                    acc[0] += f0.x * w; acc[1] += f0.y * w; acc[2] += f1.x * w; acc[3] += f1.y * w;
                } else {
                    unsigned u = *(const unsigned*)(hp + (size_t)s * K + lane * 2);
                    float2 f0 = __half22float2(*reinterpret_cast<__half2*>(&u));
                    acc[0] += f0.x * w; acc[1] += f0.y * w;
                }
            }
#pragma unroll
            for (int v = 0; v < VPL; v += 2) {
                __half2 hh = __floats2half2_rn(acc[v], acc[v + 1]);
                *(__half2*)&shA[lr * Kp + lane * VPL + v] = hh;
            }
        } else {
#pragma unroll
            for (int v = 0; v < VPL; v += 2)
                *(__half2*)&shA[lr * Kp + lane * VPL + v] = __floats2half2_rn(0.f, 0.f);
        }
    }
    __syncthreads();

    // ---- phase B: WMMA from smem ----
    {
        wmma::fragment<wmma::matrix_a, 16, 16, 16, __half, wmma::row_major> fa[RT];
        wmma::fragment<wmma::matrix_b, 16, 16, 16, __half, wmma::row_major> fb;
        wmma::fragment<wmma::accumulator, 16, 16, 16, float> fc[RT];
#pragma unroll
        for (int rt = 0; rt < RT; rt++) wmma::fill_fragment(fc[rt], 0.0f);
#pragma unroll
        for (int k = 0; k < K; k += 16) {
            wmma::load_matrix_sync(fb, sW + k * Cp + wid * 16, Cp);
#pragma unroll
            for (int rt = 0; rt < RT; rt++) {
                wmma::load_matrix_sync(fa[rt], shA + rt * 16 * Kp + k, Kp);
                wmma::mma_sync(fc[rt], fa[rt], fb, fc[rt]);
            }
        }
        __syncthreads();  // all warps done reading sW before sC overwrite
#pragma unroll
        for (int rt = 0; rt < RT; rt++)
            wmma::store_matrix_sync(sC + rt * 16 * Cp4 + wid * 16, fc[rt], Cp4,
                                    wmma::mem_row_major);
    }
    __syncthreads();

    // ---- epilogue: bias + relu (+ pool) from sC ----
    int tc = tid & 63, ty = tid >> 6;
    float2 bb = *(const float2*)&b[2 * tc];
    if (!POOL) {
#pragma unroll
        for (int r = 0; r < RPE; r++) {
            int lr = ty * RPE + r;
            int row = row0 + lr;
            if (row < n) {
                float xv = sC[lr * Cp4 + 2 * tc] + bb.x;
                float yv = sC[lr * Cp4 + 2 * tc + 1] + bb.y;
                __half2 o = __floats2half2_rn(fmaxf(xv, 0.0f), fmaxf(yv, 0.0f));
                *(__half2*)&g_h1[(size_t)row * C + 2 * tc] = o;
            }
        }
    } else {
        int curg = -1;
        float rx = 0.0f, ry = 0.0f;
#pragma unroll
        for (int r = 0; r < RPE; r++) {
            int lr = ty * RPE + r;
            int row = row0 + lr;
            if (row >= n) break;
            float xv = fmaxf(sC[lr * Cp4 + 2 * tc] + bb.x, 0.0f);
            float yv = fmaxf(sC[lr * Cp4 + 2 * tc + 1] + bb.y, 0.0f);
            int g = __ldg(&batch[row]);
            if (g != curg) {
                if (curg >= 0) {
                    atomicAdd(&g_psum[curg * 128 + 2 * tc], rx);
                    atomicAdd(&g_psum[curg * 128 + 2 * tc + 1], ry);
                }
                curg = g; rx = 0.0f; ry = 0.0f;
            }
            rx += xv; ry += yv;
        }
        if (curg >= 0) {
            atomicAdd(&g_psum[curg * 128 + 2 * tc], rx);
            atomicAdd(&g_psum[curg * 128 + 2 * tc + 1], ry);
        }
    }
}

// ---------------- MLP head ----------------
__global__ void k_fc(const float* __restrict__ Wf1, const float* __restrict__ bf1,
                     const float* __restrict__ Wf2, const float* __restrict__ bf2,
                     float* __restrict__ out) {
    int g = blockIdx.x;
    int t = threadIdx.x;  // 128
    __shared__ float p[128];
    __shared__ float f1[64];
    float inv = 1.0f / fmaxf(g_pcnt[g], 1.0f);
    p[t] = g_psum[g * 128 + t] * inv;
    __syncthreads();
    if (t < 64) {
        float acc = bf1[t];
#pragma unroll
        for (int k = 0; k < 128; k++) acc += p[k] * Wf1[k * 64 + t];
        f1[t] = fmaxf(acc, 0.0f);
    }
    __syncthreads();
    if (t < 10) {
        float acc = bf2[t];
#pragma unroll
        for (int k = 0; k < 64; k++) acc += f1[k] * Wf2[k * 10 + t];
        out[g * 10 + t] = acc;
    }
}

extern "C" void kernel_launch(void* const* d_in, const int* in_sizes, int n_in,
                              void* d_out, int out_size) {
    const float* x   = (const float*)d_in[0];
    const int* ei    = (const int*)d_in[1];
    const int* batch = (const int*)d_in[2];
    const float* W1  = (const float*)d_in[3];
    const float* b1  = (const float*)d_in[4];
    const float* W2  = (const float*)d_in[5];
    const float* b2  = (const float*)d_in[6];
    const float* W3  = (const float*)d_in[7];
    const float* b3  = (const float*)d_in[8];
    const float* Wf1 = (const float*)d_in[9];
    const float* bf1 = (const float*)d_in[10];
    const float* Wf2 = (const float*)d_in[11];
    const float* bf2 = (const float*)d_in[12];
    float* out = (float*)d_out;

    int N = in_sizes[0] / 3;
    int E = in_sizes[1] / 2;
    const int* src = ei;
    const int* dst = ei + E;
    int NB = (N + SCAN_B - 1) / SCAN_B;  // <= 49

    // single-wave prep (zero + convert + CSR build)
    k_prep<<<NB, SCAN_B>>>(src, dst, batch, W2, W3, x, N, E);

    // Fused layers (per-K measured-optimal tile sizes)
    k_layer1<<<(N + 63) / 64, 256>>>(W1, b1, N);
    k_layer<64, 2, 16, false><<<(N + 15) / 16, 256>>>(b2, batch, N);
    k_layer<128, 4, 32, true><<<(N + 31) / 32, 256>>>(b3, batch, N);

    // Head
    k_fc<<<GRAPHS, 128>>>(Wf1, bf1, Wf2, bf2, out);
}

// round 16
// speedup vs baseline: 1.4637x; 1.0521x over previous
#include <cuda_runtime.h>
#include <cuda_bf16.h>
#include <cuda_fp16.h>
#include <mma.h>

using namespace nvcuda;

#define NMAX 50000
#define EMAX 800000
#define GRAPHS 64
#define SCAN_B 1024

// ---------------- device scratch (allocation-free rule) ----------------
static __device__ __half g_h0[NMAX * 64];   // layer-1 output, fp16
static __device__ __half g_h1[NMAX * 128];  // layer-2 output, fp16
// W2/W3 in fp16, TILE-CONTIGUOUS layout: tile (kt, ct) of 16x16 stored
// row-major at offset (kt*8 + ct)*256. Fragment loads become 512B contiguous.
static __device__ __half g_w2t[64 * 128];
static __device__ __half g_w3t[128 * 128];
static __device__ float4 g_x4[NMAX];        // x padded to float4
static __device__ float g_dinv[NMAX];
static __device__ int   g_cnt[NMAX];
static __device__ int   g_rowptr[NMAX + 1];
static __device__ int   g_cursor[NMAX];
static __device__ int   g_bsum[64];
static __device__ int   g_sync;             // zero-init at load; self-reset per launch
static __device__ unsigned long long g_edge[EMAX];  // packed {norm<<32 | src}
static __device__ float g_psum[GRAPHS * 128];
static __device__ float g_pcnt[GRAPHS];

typedef unsigned long long ull;

__device__ __forceinline__ void eunpack(ull r, int& s, float& w) {
    s = (int)(unsigned)r;
    w = __uint_as_float((unsigned)(r >> 32));
}

// spin grid barrier helper (t==0 arrives; all threads blocked by syncthreads)
__device__ __forceinline__ void grid_bar(int t, int target) {
    __threadfence();
    __syncthreads();
    if (t == 0) {
        atomicAdd(&g_sync, 1);
        while (atomicAdd(&g_sync, 0) < target) { }
    }
    __syncthreads();
}

// Single-wave prep: zero/convert/tile-W -> count -> scan -> fill.
__global__ void __launch_bounds__(1024) k_prep(const int* __restrict__ src,
                                               const int* __restrict__ dst,
                                               const int* __restrict__ batch,
                                               const float* __restrict__ W2,
                                               const float* __restrict__ W3,
                                               const float* __restrict__ x,
                                               int n, int E) {
    __shared__ int swarp[32];
    __shared__ int pref[64];
    __shared__ int wtot;
    int t = threadIdx.x;
    int lane = t & 31, wid = t >> 5;
    int nb = gridDim.x;
    int gtid = blockIdx.x * SCAN_B + t;
    int nthr = nb * SCAN_B;

    // ---- phase 0: zero + fp16 W tiling + x padding ----
    for (int i = gtid; i < n; i += nthr) {
        g_cnt[i] = 0;
        g_x4[i] = make_float4(x[i * 3], x[i * 3 + 1], x[i * 3 + 2], 0.0f);
    }
    if (gtid < GRAPHS * 128) g_psum[gtid] = 0.0f;
    if (gtid < GRAPHS) g_pcnt[gtid] = 0.0f;
    if (gtid < 64 * 128) {
        int k = gtid >> 7, c = gtid & 127;
        int d = ((k >> 4) * 8 + (c >> 4)) * 256 + (k & 15) * 16 + (c & 15);
        g_w2t[d] = __float2half(W2[gtid]);
    }
    if (gtid < 128 * 128) {
        int k = gtid >> 7, c = gtid & 127;
        int d = ((k >> 4) * 8 + (c >> 4)) * 256 + (k & 15) * 16 + (c & 15);
        g_w3t[d] = __float2half(W3[gtid]);
    }
    grid_bar(t, nb);

    // ---- phase 1: histograms ----
    for (int e = gtid; e < E; e += nthr) atomicAdd(&g_cnt[dst[e]], 1);
    for (int i = gtid; i < n; i += nthr) atomicAdd(&g_pcnt[batch[i]], 1.0f);
    grid_bar(t, 2 * nb);

    // ---- phase 2: local scan + dinv ----
    int i = gtid;
    int v = (i < n) ? g_cnt[i] : 0;
    if (i < n) g_dinv[i] = rsqrtf((float)v + 1.0f);
    int incl = v;
#pragma unroll
    for (int off = 1; off < 32; off <<= 1) {
        int y = __shfl_up_sync(0xffffffffu, incl, off);
        if (lane >= off) incl += y;
    }
    if (lane == 31) swarp[wid] = incl;
    __syncthreads();
    if (wid == 0) {
        int w = swarp[lane];
#pragma unroll
        for (int off = 1; off < 32; off <<= 1) {
            int y = __shfl_up_sync(0xffffffffu, w, off);
            if (lane >= off) w += y;
        }
        swarp[lane] = w;
    }
    __syncthreads();
    int excl = incl - v + ((wid > 0) ? swarp[wid - 1] : 0);
    if (t == SCAN_B - 1) g_bsum[blockIdx.x] = excl + v;
    grid_bar(t, 3 * nb);

    // ---- phase 3: prefix block totals, write rowptr/cursor ----
    if (t < 64) {
        int bv = (t < nb) ? g_bsum[t] : 0;
        int binc = bv;
#pragma unroll
        for (int off = 1; off < 32; off <<= 1) {
            int y = __shfl_up_sync(0xffffffffu, binc, off);
            if (lane >= off) binc += y;
        }
        pref[t] = binc - bv;
        if (t == 31) wtot = binc;
    }
    __syncthreads();
    if (t >= 32 && t < 64) pref[t] += wtot;
    __syncthreads();
    if (i < n) {
        int rp = excl + pref[blockIdx.x];
        g_rowptr[i] = rp;
        g_cursor[i] = rp;
    }
    if (gtid == 0) g_rowptr[n] = E;
    grid_bar(t, 4 * nb);

    // ---- phase 4: fill packed edge records ----
    for (int e = gtid; e < E; e += nthr) {
        int s = src[e], d = dst[e];
        int pos = atomicAdd(&g_cursor[d], 1);
        float nm = g_dinv[s] * g_dinv[d];
        g_edge[pos] = ((ull)__float_as_uint(nm) << 32) | (unsigned)s;
    }

    // ---- final: self-reset g_sync ----
    __threadfence();
    __syncthreads();
    if (t == 0) {
        int tk = atomicAdd(&g_sync, 1);
        if (tk == 5 * nb - 1) g_sync = 0;
    }
}

// ---------------- Layer 1 fused: agg(C=3) + 3->64 GEMM + relu -> g_h0 -------
__global__ void __launch_bounds__(256) k_layer1(const float* __restrict__ W,
                                                const float* __restrict__ b, int n) {
    const int NPB = 64;
    __shared__ float sa[NPB][3];
    __shared__ float sW[192];
    __shared__ float sb[64];
    int tid = threadIdx.x, wid = tid >> 5, lane = tid & 31;
    int node0 = blockIdx.x * NPB;
    if (tid < 192) sW[tid] = W[tid];
    if (tid < 64) sb[tid] = b[tid];

    for (int k = 0; k < NPB; k += 8) {
        int lr = k + wid;
        int i = node0 + lr;
        if (i < n) {
            int beg = g_rowptr[i], end = g_rowptr[i + 1];
            float a0 = 0.f, a1 = 0.f, a2 = 0.f;
            for (int j = beg + lane; j < end; j += 32) {
                int s; float w; eunpack(g_edge[j], s, w);
                float4 xv = g_x4[s];
                a0 += xv.x * w;
                a1 += xv.y * w;
                a2 += xv.z * w;
            }
#pragma unroll
            for (int off = 16; off > 0; off >>= 1) {
                a0 += __shfl_down_sync(0xffffffffu, a0, off);
                a1 += __shfl_down_sync(0xffffffffu, a1, off);
                a2 += __shfl_down_sync(0xffffffffu, a2, off);
            }
            if (lane == 0) {
                float di = g_dinv[i], sw = di * di;
                float4 xv = g_x4[i];
                sa[lr][0] = a0 + xv.x * sw;
                sa[lr][1] = a1 + xv.y * sw;
                sa[lr][2] = a2 + xv.z * sw;
            }
        }
    }
    __syncthreads();

    int tc = tid & 63, ty = tid >> 6;
    float w0 = sW[tc], w1 = sW[64 + tc], w2 = sW[128 + tc], bb = sb[tc];
#pragma unroll 4
    for (int r = 0; r < 16; r++) {
        int lr = ty * 16 + r;
        int row = node0 + lr;
        if (row >= n) break;
        float v = bb + sa[lr][0] * w0 + sa[lr][1] * w1 + sa[lr][2] * w2;
        g_h0[row * 64 + tc] = __float2half(fmaxf(v, 0.0f));
    }
}

// ---------------- Fused layer: agg(K) + KxC GEMM via WMMA (+relu) ----------
// K in {64,128}, C=128. Block: 256 thr, ROWS nodes.
// Phase A: warp aggregates ROWS/8 nodes (fp32 accum), stores fp16 to padded shA.
// Phase B: fb fragments loaded DIRECTLY from tile-contiguous global W (512B
// contiguous per fragment, L1-resident after first block per SM). No sW stage
// -> smem 10.7/25.6KB -> 8 blocks/SM.
template <int K, int VPL, int ROWS, bool POOL>
__global__ void __launch_bounds__(256) k_layer(const float* __restrict__ b,
                                               const int* __restrict__ batch, int n) {
    const int C = 128;
    const int Kp = K + 8;      // half elems; row stride mult of 16B
    const int Cp4 = 132;       // float elems; 528B row stride
    const int NPW = ROWS / 8;  // nodes per warp in phase A
    const int RT = ROWS / 16;  // row tiles in phase B
    const int RPE = ROWS / 4;  // rows per ty group in epilogue
    __shared__ __align__(16) __half shA[ROWS * Kp];
    __shared__ __align__(16) float sC[ROWS * Cp4];

    int tid = threadIdx.x, wid = tid >> 5, lane = tid & 31;
    int row0 = blockIdx.x * ROWS;
    const __half* __restrict__ hp = (K == 64) ? g_h0 : g_h1;
    const __half* __restrict__ Wt = (K == 64) ? g_w2t : g_w3t;

    // ---- phase A: aggregation ----
#pragma unroll
    for (int rr = 0; rr < NPW; rr++) {
        int lr = wid * NPW + rr;
        int i = row0 + lr;
        if (i < n) {
            int beg = g_rowptr[i], end = g_rowptr[i + 1];
            float di = g_dinv[i], sw = di * di;
            float acc[VPL];
            if (VPL == 4) {
                uint2 u = *(const uint2*)(hp + (size_t)i * K + lane * 4);
                float2 f0 = __half22float2(*reinterpret_cast<__half2*>(&u.x));
                float2 f1 = __half22float2(*reinterpret_cast<__half2*>(&u.y));
                acc[0] = f0.x * sw; acc[1] = f0.y * sw; acc[2] = f1.x * sw; acc[3] = f1.y * sw;
            } else {
                unsigned u = *(const unsigned*)(hp + (size_t)i * K + lane * 2);
                float2 f0 = __half22float2(*reinterpret_cast<__half2*>(&u));
                acc[0] = f0.x * sw; acc[1] = f0.y * sw;
            }
            int j = beg;
            for (; j + 4 <= end; j += 4) {
                int s0, s1, s2, s3; float w0, w1, w2, w3;
                eunpack(g_edge[j], s0, w0);
                eunpack(g_edge[j + 1], s1, w1);
                eunpack(g_edge[j + 2], s2, w2);
                eunpack(g_edge[j + 3], s3, w3);
                if (VPL == 4) {
                    uint2 u0 = *(const uint2*)(hp + (size_t)s0 * K + lane * 4);
                    uint2 u1 = *(const uint2*)(hp + (size_t)s1 * K + lane * 4);
                    uint2 u2 = *(const uint2*)(hp + (size_t)s2 * K + lane * 4);
                    uint2 u3 = *(const uint2*)(hp + (size_t)s3 * K + lane * 4);
                    float2 a0 = __half22float2(*reinterpret_cast<__half2*>(&u0.x));
                    float2 b0 = __half22float2(*reinterpret_cast<__half2*>(&u0.y));
                    float2 a1 = __half22float2(*reinterpret_cast<__half2*>(&u1.x));
                    float2 b1 = __half22float2(*reinterpret_cast<__half2*>(&u1.y));
                    float2 a2 = __half22float2(*reinterpret_cast<__half2*>(&u2.x));
                    float2 b2 = __half22float2(*reinterpret_cast<__half2*>(&u2.y));
                    float2 a3 = __half22float2(*reinterpret_cast<__half2*>(&u3.x));
                    float2 b3 = __half22float2(*reinterpret_cast<__half2*>(&u3.y));
                    acc[0] += a0.x * w0 + a1.x * w1 + a2.x * w2 + a3.x * w3;
                    acc[1] += a0.y * w0 + a1.y * w1 + a2.y * w2 + a3.y * w3;
                    acc[2] += b0.x * w0 + b1.x * w1 + b2.x * w2 + b3.x * w3;
                    acc[3] += b0.y * w0 + b1.y * w1 + b2.y * w2 + b3.y * w3;
                } else {
                    unsigned u0 = *(const unsigned*)(hp + (size_t)s0 * K + lane * 2);
                    unsigned u1 = *(const unsigned*)(hp + (size_t)s1 * K + lane * 2);
                    unsigned u2 = *(const unsigned*)(hp + (size_t)s2 * K + lane * 2);
                    unsigned u3 = *(const unsigned*)(hp + (size_t)s3 * K + lane * 2);
                    float2 a0 = __half22float2(*reinterpret_cast<__half2*>(&u0));
                    float2 a1 = __half22float2(*reinterpret_cast<__half2*>(&u1));
                    float2 a2 = __half22float2(*reinterpret_cast<__half2*>(&u2));
                    float2 a3 = __half22float2(*reinterpret_cast<__half2*>(&u3));
                    acc[0] += a0.x * w0 + a1.x * w1 + a2.x * w2 + a3.x * w3;
                    acc[1] += a0.y * w0 + a1.y * w1 + a2.y * w2 + a3.y * w3;
                }
            }
            for (; j < end; j++) {
                int s; float w; eunpack(g_edge[j], s, w);
                if (VPL == 4) {
                    uint2 u = *(const uint2*)(hp + (size_t)s * K + lane * 4);
                    float2 f0 = __half22float2(*reinterpret_cast<__half2*>(&u.x));
                    float2 f1 = __half22float2(*reinterpret_cast<__half2*>(&u.y));
                    acc[0] += f0.x * w; acc[1] += f0.y * w; acc[2] += f1.x * w; acc[3] += f1.y * w;
                } else {
                    unsigned u = *(const unsigned*)(hp + (size_t)s * K + lane * 2);
                    float2 f0 = __half22float2(*reinterpret_cast<__half2*>(&u));
                    acc[0] += f0.x * w; acc[1] += f0.y * w;
                }
            }
#pragma unroll
            for (int v = 0; v < VPL; v += 2) {
                __half2 hh = __floats2half2_rn(acc[v], acc[v + 1]);
                *(__half2*)&shA[lr * Kp + lane * VPL + v] = hh;
            }
        } else {
#pragma unroll
            for (int v = 0; v < VPL; v += 2)
                *(__half2*)&shA[lr * Kp + lane * VPL + v] = __floats2half2_rn(0.f, 0.f);
        }
    }
    __syncthreads();

    // ---- phase B: WMMA; fa from smem, fb from tile-contiguous global W ----
    {
        wmma::fragment<wmma::matrix_a, 16, 16, 16, __half, wmma::row_major> fa[RT];
        wmma::fragment<wmma::matrix_b, 16, 16, 16, __half, wmma::row_major> fb;
        wmma::fragment<wmma::accumulator, 16, 16, 16, float> fc[RT];
#pragma unroll
        for (int rt = 0; rt < RT; rt++) wmma::fill_fragment(fc[rt], 0.0f);
#pragma unroll
        for (int k = 0; k < K; k += 16) {
            // tile (kt = k/16, ct = wid): 512 contiguous bytes
            wmma::load_matrix_sync(fb, Wt + ((k >> 4) * 8 + wid) * 256, 16);
#pragma unroll
            for (int rt = 0; rt < RT; rt++) {
                wmma::load_matrix_sync(fa[rt], shA + rt * 16 * Kp + k, Kp);
                wmma::mma_sync(fc[rt], fa[rt], fb, fc[rt]);
            }
        }
#pragma unroll
        for (int rt = 0; rt < RT; rt++)
            wmma::store_matrix_sync(sC + rt * 16 * Cp4 + wid * 16, fc[rt], Cp4,
                                    wmma::mem_row_major);
    }
    __syncthreads();

    // ---- epilogue: bias + relu (+ pool) from sC ----
    int tc = tid & 63, ty = tid >> 6;
    float2 bb = *(const float2*)&b[2 * tc];
    if (!POOL) {
#pragma unroll
        for (int r = 0; r < RPE; r++) {
            int lr = ty * RPE + r;
            int row = row0 + lr;
            if (row < n) {
                float xv = sC[lr * Cp4 + 2 * tc] + bb.x;
                float yv = sC[lr * Cp4 + 2 * tc + 1] + bb.y;
                __half2 o = __floats2half2_rn(fmaxf(xv, 0.0f), fmaxf(yv, 0.0f));
                *(__half2*)&g_h1[(size_t)row * C + 2 * tc] = o;
            }
        }
    } else {
        int curg = -1;
        float rx = 0.0f, ry = 0.0f;
#pragma unroll
        for (int r = 0; r < RPE; r++) {
            int lr = ty * RPE + r;
            int row = row0 + lr;
            if (row >= n) break;
            float xv = fmaxf(sC[lr * Cp4 + 2 * tc] + bb.x, 0.0f);
            float yv = fmaxf(sC[lr * Cp4 + 2 * tc + 1] + bb.y, 0.0f);
            int g = __ldg(&batch[row]);
            if (g != curg) {
                if (curg >= 0) {
                    atomicAdd(&g_psum[curg * 128 + 2 * tc], rx);
                    atomicAdd(&g_psum[curg * 128 + 2 * tc + 1], ry);
                }
                curg = g; rx = 0.0f; ry = 0.0f;
            }
            rx += xv; ry += yv;
        }
        if (curg >= 0) {
            atomicAdd(&g_psum[curg * 128 + 2 * tc], rx);
            atomicAdd(&g_psum[curg * 128 + 2 * tc + 1], ry);
        }
    }
}

// ---------------- MLP head ----------------
__global__ void k_fc(const float* __restrict__ Wf1, const float* __restrict__ bf1,
                     const float* __restrict__ Wf2, const float* __restrict__ bf2,
                     float* __restrict__ out) {
    int g = blockIdx.x;
    int t = threadIdx.x;  // 128
    __shared__ float p[128];
    __shared__ float f1[64];
    float inv = 1.0f / fmaxf(g_pcnt[g], 1.0f);
    p[t] = g_psum[g * 128 + t] * inv;
    __syncthreads();
    if (t < 64) {
        float acc = bf1[t];
#pragma unroll
        for (int k = 0; k < 128; k++) acc += p[k] * Wf1[k * 64 + t];
        f1[t] = fmaxf(acc, 0.0f);
    }
    __syncthreads();
    if (t < 10) {
        float acc = bf2[t];
#pragma unroll
        for (int k = 0; k < 64; k++) acc += f1[k] * Wf2[k * 10 + t];
        out[g * 10 + t] = acc;
    }
}

extern "C" void kernel_launch(void* const* d_in, const int* in_sizes, int n_in,
                              void* d_out, int out_size) {
    const float* x   = (const float*)d_in[0];
    const int* ei    = (const int*)d_in[1];
    const int* batch = (const int*)d_in[2];
    const float* W1  = (const float*)d_in[3];
    const float* b1  = (const float*)d_in[4];
    const float* W2  = (const float*)d_in[5];
    const float* b2  = (const float*)d_in[6];
    const float* W3  = (const float*)d_in[7];
    const float* b3  = (const float*)d_in[8];
    const float* Wf1 = (const float*)d_in[9];
    const float* bf1 = (const float*)d_in[10];
    const float* Wf2 = (const float*)d_in[11];
    const float* bf2 = (const float*)d_in[12];
    float* out = (float*)d_out;

    int N = in_sizes[0] / 3;
    int E = in_sizes[1] / 2;
    const int* src = ei;
    const int* dst = ei + E;
    int NB = (N + SCAN_B - 1) / SCAN_B;  // <= 49

    // single-wave prep (zero + W tiling + CSR build)
    k_prep<<<NB, SCAN_B>>>(src, dst, batch, W2, W3, x, N, E);

    // Fused layers (per-K measured-optimal tile sizes)
    k_layer1<<<(N + 63) / 64, 256>>>(W1, b1, N);
    k_layer<64, 2, 16, false><<<(N + 15) / 16, 256>>>(b2, batch, N);
    k_layer<128, 4, 32, true><<<(N + 31) / 32, 256>>>(b3, batch, N);

    // Head
    k_fc<<<GRAPHS, 128>>>(Wf1, bf1, Wf2, bf2, out);
}